// round 2
// baseline (speedup 1.0000x reference)
#include <cuda_runtime.h>
#include <math.h>

// Problem constants
#define B_   2
#define S_   2048
#define D_   1024
#define H_   16
#define DH_  64
#define M_   (B_*S_)          // 4096 rows for all projections

// ---------------- scratch (device globals; no allocation) ----------------
__device__ float g_q[B_*H_*S_*DH_];     // [B,H,S,DH]
__device__ float g_k[B_*H_*S_*DH_];
__device__ float g_v[B_*H_*S_*DH_];
__device__ float g_att[B_*S_*D_];       // [B,S,D]

// =====================================================================
// GEMM: C[m][n] = sum_k A[m][k] * W[n][k] + bias[n]   (torch Linear, NT)
// M=4096, N=1024, K=1024 fixed. BM=BN=128, BK=16, 256 threads, 8x8/thread.
// MODE 0: plain row-major [M][N] output (final projection -> d_out)
// MODE 1: scatter to [B,H,S,DH] (q/k/v scratch)
// =====================================================================
#define BM 128
#define BN 128
#define BK 16
#define ALD 132   // padded leading dim (floats); 132*4=528B, 16B-aligned rows

template<int MODE>
__global__ void __launch_bounds__(256, 2) gemm_kernel(
    const float* __restrict__ A, const float* __restrict__ W,
    const float* __restrict__ bias, float* __restrict__ out)
{
    __shared__ float As[BK][ALD];
    __shared__ float Bs[BK][ALD];

    const int tid = threadIdx.x;
    const int tx = tid & 15;        // n-dim group (8 cols each)
    const int ty = tid >> 4;        // m-dim group (8 rows each)
    const int m0 = blockIdx.y * BM;
    const int n0 = blockIdx.x * BN;

    float acc[8][8];
    #pragma unroll
    for (int i = 0; i < 8; i++)
        #pragma unroll
        for (int j = 0; j < 8; j++) acc[i][j] = 0.f;

    // register prefetch buffers (A tile and W tile are each 128x16 = 512 float4)
    float4 pa[2], pb[2];
    #pragma unroll
    for (int u = 0; u < 2; u++) {
        int idx = u*256 + tid;
        int r = idx >> 2, c4 = idx & 3;
        pa[u] = *(const float4*)&A[(size_t)(m0 + r)*1024 + c4*4];
        pb[u] = *(const float4*)&W[(size_t)(n0 + r)*1024 + c4*4];
    }

    for (int kt = 0; kt < 1024/BK; kt++) {
        // commit prefetched tile to smem (transposed: [k][m] / [k][n])
        #pragma unroll
        for (int u = 0; u < 2; u++) {
            int idx = u*256 + tid;
            int r = idx >> 2, c4 = idx & 3;
            As[c4*4+0][r] = pa[u].x; As[c4*4+1][r] = pa[u].y;
            As[c4*4+2][r] = pa[u].z; As[c4*4+3][r] = pa[u].w;
            Bs[c4*4+0][r] = pb[u].x; Bs[c4*4+1][r] = pb[u].y;
            Bs[c4*4+2][r] = pb[u].z; Bs[c4*4+3][r] = pb[u].w;
        }
        __syncthreads();
        if (kt + 1 < 1024/BK) {
            int k0 = (kt+1)*BK;
            #pragma unroll
            for (int u = 0; u < 2; u++) {
                int idx = u*256 + tid;
                int r = idx >> 2, c4 = idx & 3;
                pa[u] = *(const float4*)&A[(size_t)(m0 + r)*1024 + k0 + c4*4];
                pb[u] = *(const float4*)&W[(size_t)(n0 + r)*1024 + k0 + c4*4];
            }
        }
        #pragma unroll
        for (int kk = 0; kk < BK; kk++) {
            float a[8], b[8];
            *(float4*)&a[0] = *(const float4*)&As[kk][ty*8];
            *(float4*)&a[4] = *(const float4*)&As[kk][ty*8+4];
            *(float4*)&b[0] = *(const float4*)&Bs[kk][tx*8];
            *(float4*)&b[4] = *(const float4*)&Bs[kk][tx*8+4];
            #pragma unroll
            for (int i = 0; i < 8; i++)
                #pragma unroll
                for (int j = 0; j < 8; j++)
                    acc[i][j] += a[i]*b[j];
        }
        __syncthreads();
    }

    // epilogue: bias + store
    float bv[8];
    *(float4*)&bv[0] = *(const float4*)&bias[n0 + tx*8];
    *(float4*)&bv[4] = *(const float4*)&bias[n0 + tx*8 + 4];

    if (MODE == 0) {
        #pragma unroll
        for (int i = 0; i < 8; i++) {
            int m = m0 + ty*8 + i;
            float4 r0, r1;
            r0.x = acc[i][0]+bv[0]; r0.y = acc[i][1]+bv[1];
            r0.z = acc[i][2]+bv[2]; r0.w = acc[i][3]+bv[3];
            r1.x = acc[i][4]+bv[4]; r1.y = acc[i][5]+bv[5];
            r1.z = acc[i][6]+bv[6]; r1.w = acc[i][7]+bv[7];
            *(float4*)&out[(size_t)m*1024 + n0 + tx*8]     = r0;
            *(float4*)&out[(size_t)m*1024 + n0 + tx*8 + 4] = r1;
        }
    } else {
        // scatter to [B,H,S,DH]: m -> (b,s), n -> (h,d). 8-col block never
        // crosses a 64 boundary, so h is constant per thread.
        int n = n0 + tx*8;
        int h = n >> 6;
        int d = n & 63;
        #pragma unroll
        for (int i = 0; i < 8; i++) {
            int m = m0 + ty*8 + i;
            int b = m >> 11;          // /2048
            int s = m & 2047;
            size_t base = (((size_t)(b*H_ + h))*S_ + s)*DH_ + d;
            float4 r0, r1;
            r0.x = acc[i][0]+bv[0]; r0.y = acc[i][1]+bv[1];
            r0.z = acc[i][2]+bv[2]; r0.w = acc[i][3]+bv[3];
            r1.x = acc[i][4]+bv[4]; r1.y = acc[i][5]+bv[5];
            r1.z = acc[i][6]+bv[6]; r1.w = acc[i][7]+bv[7];
            *(float4*)&out[base]     = r0;
            *(float4*)&out[base + 4] = r1;
        }
    }
}

// =====================================================================
// Fused flash attention, fp32. One block = one (b,h) x 128-query tile.
// Loop over key tiles of 128: S = Q K^T (8x8 register tile, 16x16 thread
// grid), online softmax (16-lane shfl row reductions), P via smem, then
// O += P*V with a remapped 32x8 thread grid (4x8 per thread).
// =====================================================================
#define AQ 128
#define AK 128
#define QLD 132     // padded LD for transposed Q/K smem
#define PLD 129     // padded LD for P smem (conflict-free broadcast reads)

// dynamic smem layout (floats):
//   Qs [64][QLD], Ks [64][QLD], Vs [128][64], Ps [128][PLD], alphas[128], lrow[128]
#define OFF_QS 0
#define OFF_KS (OFF_QS + 64*QLD)
#define OFF_VS (OFF_KS + 64*QLD)
#define OFF_PS (OFF_VS + AK*DH_)
#define OFF_AL (OFF_PS + AQ*PLD)
#define OFF_LR (OFF_AL + AQ)
#define ATTN_SMEM_FLOATS (OFF_LR + AQ)
#define ATTN_SMEM_BYTES (ATTN_SMEM_FLOATS * 4)

__global__ void __launch_bounds__(256, 1) attn_kernel()
{
    extern __shared__ float sm[];
    float* Qs = sm + OFF_QS;
    float* Ks = sm + OFF_KS;
    float* Vs = sm + OFF_VS;
    float* Ps = sm + OFF_PS;
    float* alphas = sm + OFF_AL;
    float* lrow = sm + OFF_LR;

    const int tid = threadIdx.x;
    const int tx = tid & 15, ty = tid >> 4;     // S-gemm mapping (16x16)
    const int tn2 = tid & 7, tm2 = tid >> 3;    // PV mapping (32x8)
    const int bh = blockIdx.y;                  // b*H + h
    const int q0 = blockIdx.x * AQ;

    const float* qbase = g_q + (size_t)bh*S_*DH_;
    const float* kbase = g_k + (size_t)bh*S_*DH_;
    const float* vbase = g_v + (size_t)bh*S_*DH_;

    // Load Q tile transposed into Qs[d][m]  (128 rows x 64 d = 2048 float4)
    #pragma unroll
    for (int u = 0; u < 8; u++) {
        int idx = u*256 + tid;
        int r = idx >> 4, c4 = idx & 15;
        float4 qv = *(const float4*)&qbase[(size_t)(q0 + r)*DH_ + c4*4];
        Qs[(c4*4+0)*QLD + r] = qv.x;
        Qs[(c4*4+1)*QLD + r] = qv.y;
        Qs[(c4*4+2)*QLD + r] = qv.z;
        Qs[(c4*4+3)*QLD + r] = qv.w;
    }

    float mrow[8], lacc[8];
    float o[4][8];
    #pragma unroll
    for (int i = 0; i < 8; i++) { mrow[i] = -INFINITY; lacc[i] = 0.f; }
    #pragma unroll
    for (int i = 0; i < 4; i++)
        #pragma unroll
        for (int j = 0; j < 8; j++) o[i][j] = 0.f;

    for (int kt = 0; kt < S_/AK; kt++) {
        __syncthreads();   // prev PV done (and Q visible on first iter)
        const int k0 = kt*AK;
        // K transposed -> Ks[d][j]; V natural -> Vs[j][d]
        #pragma unroll
        for (int u = 0; u < 8; u++) {
            int idx = u*256 + tid;
            int r = idx >> 4, c4 = idx & 15;
            float4 kv = *(const float4*)&kbase[(size_t)(k0 + r)*DH_ + c4*4];
            Ks[(c4*4+0)*QLD + r] = kv.x;
            Ks[(c4*4+1)*QLD + r] = kv.y;
            Ks[(c4*4+2)*QLD + r] = kv.z;
            Ks[(c4*4+3)*QLD + r] = kv.w;
            float4 vv = *(const float4*)&vbase[(size_t)(k0 + r)*DH_ + c4*4];
            *(float4*)&Vs[r*DH_ + c4*4] = vv;
        }
        __syncthreads();

        // ---- S = Q K^T ----
        float s[8][8];
        #pragma unroll
        for (int i = 0; i < 8; i++)
            #pragma unroll
            for (int j = 0; j < 8; j++) s[i][j] = 0.f;

        #pragma unroll 16
        for (int d = 0; d < DH_; d++) {
            float a[8], b[8];
            *(float4*)&a[0] = *(const float4*)&Qs[d*QLD + ty*8];
            *(float4*)&a[4] = *(const float4*)&Qs[d*QLD + ty*8 + 4];
            *(float4*)&b[0] = *(const float4*)&Ks[d*QLD + tx*8];
            *(float4*)&b[4] = *(const float4*)&Ks[d*QLD + tx*8 + 4];
            #pragma unroll
            for (int i = 0; i < 8; i++)
                #pragma unroll
                for (int j = 0; j < 8; j++)
                    s[i][j] += a[i]*b[j];
        }

        // ---- online softmax (rows owned by 16 consecutive lanes) ----
        #pragma unroll
        for (int i = 0; i < 8; i++) {
            #pragma unroll
            for (int j = 0; j < 8; j++) s[i][j] *= 0.125f;  // 1/sqrt(64)
            float mx = s[i][0];
            #pragma unroll
            for (int j = 1; j < 8; j++) mx = fmaxf(mx, s[i][j]);
            #pragma unroll
            for (int off = 8; off >= 1; off >>= 1)
                mx = fmaxf(mx, __shfl_xor_sync(0xffffffffu, mx, off));
            float mnew = fmaxf(mrow[i], mx);
            float alpha = __expf(mrow[i] - mnew);
            mrow[i] = mnew;
            float sum = 0.f;
            #pragma unroll
            for (int j = 0; j < 8; j++) {
                s[i][j] = __expf(s[i][j] - mnew);
                sum += s[i][j];
            }
            #pragma unroll
            for (int off = 8; off >= 1; off >>= 1)
                sum += __shfl_xor_sync(0xffffffffu, sum, off);
            lacc[i] = lacc[i]*alpha + sum;

            int r = ty*8 + i;
            #pragma unroll
            for (int j = 0; j < 8; j++) Ps[r*PLD + tx*8 + j] = s[i][j];
            if (tx == 0) { alphas[r] = alpha; lrow[r] = lacc[i]; }
        }
        __syncthreads();

        // ---- O = O*alpha + P V  (remapped 32x8 grid, 4 rows x 8 cols) ----
        float al[4];
        #pragma unroll
        for (int i = 0; i < 4; i++) al[i] = alphas[tm2*4 + i];
        #pragma unroll
        for (int i = 0; i < 4; i++)
            #pragma unroll
            for (int j = 0; j < 8; j++) o[i][j] *= al[i];

        #pragma unroll 16
        for (int j = 0; j < AK; j++) {
            float p[4];
            #pragma unroll
            for (int i = 0; i < 4; i++) p[i] = Ps[(tm2*4 + i)*PLD + j];
            float vv[8];
            *(float4*)&vv[0] = *(const float4*)&Vs[j*DH_ + tn2*8];
            *(float4*)&vv[4] = *(const float4*)&Vs[j*DH_ + tn2*8 + 4];
            #pragma unroll
            for (int i = 0; i < 4; i++)
                #pragma unroll
                for (int jj = 0; jj < 8; jj++)
                    o[i][jj] += p[i]*vv[jj];
        }
    }

    // ---- normalize + write to g_att [B,S,D] ----
    const int b = bh >> 4, h = bh & 15;
    #pragma unroll
    for (int i = 0; i < 4; i++) {
        int m = tm2*4 + i;
        float linv = 1.0f / lrow[m];
        float4 r0, r1;
        r0.x = o[i][0]*linv; r0.y = o[i][1]*linv;
        r0.z = o[i][2]*linv; r0.w = o[i][3]*linv;
        r1.x = o[i][4]*linv; r1.y = o[i][5]*linv;
        r1.z = o[i][6]*linv; r1.w = o[i][7]*linv;
        size_t off = ((size_t)(b*S_ + q0 + m))*D_ + h*DH_ + tn2*8;
        *(float4*)&g_att[off]     = r0;
        *(float4*)&g_att[off + 4] = r1;
    }
}

// =====================================================================
// Launch
// =====================================================================
extern "C" void kernel_launch(void* const* d_in, const int* in_sizes, int n_in,
                              void* d_out, int out_size)
{
    const float* query  = (const float*)d_in[0];
    const float* keys   = (const float*)d_in[1];
    const float* values = (const float*)d_in[2];
    const float* Wq = (const float*)d_in[3];
    const float* bq = (const float*)d_in[4];
    const float* Wk = (const float*)d_in[5];
    const float* bk = (const float*)d_in[6];
    const float* Wv = (const float*)d_in[7];
    const float* bv = (const float*)d_in[8];
    const float* Wo = (const float*)d_in[9];
    const float* bo = (const float*)d_in[10];
    float* out = (float*)d_out;

    float *qp, *kp, *vp, *ap;
    cudaGetSymbolAddress((void**)&qp, g_q);
    cudaGetSymbolAddress((void**)&kp, g_k);
    cudaGetSymbolAddress((void**)&vp, g_v);
    cudaGetSymbolAddress((void**)&ap, g_att);

    cudaFuncSetAttribute(attn_kernel,
                         cudaFuncAttributeMaxDynamicSharedMemorySize,
                         ATTN_SMEM_BYTES);

    dim3 gemm_grid(D_/BN, M_/BM);   // (8, 32)
    gemm_kernel<1><<<gemm_grid, 256>>>(query,  Wq, bq, qp);
    gemm_kernel<1><<<gemm_grid, 256>>>(keys,   Wk, bk, kp);
    gemm_kernel<1><<<gemm_grid, 256>>>(values, Wv, bv, vp);

    attn_kernel<<<dim3(S_/AQ, B_*H_), 256, ATTN_SMEM_BYTES>>>();

    gemm_kernel<0><<<gemm_grid, 256>>>(ap, Wo, bo, out);
}

// round 5
// speedup vs baseline: 1.2937x; 1.2937x over previous
#include <cuda_runtime.h>
#include <cuda_fp16.h>
#include <mma.h>
#include <math.h>
#include <stdint.h>

using namespace nvcuda;

// Problem constants
#define B_   2
#define S_   2048
#define D_   1024
#define H_   16
#define DH_  64
#define M_   (B_*S_)          // 4096 rows for all projections

// ---------------- scratch (device globals; no allocation) ----------------
__device__ float g_q[B_*H_*S_*DH_];     // [B,H,S,DH]
__device__ float g_k[B_*H_*S_*DH_];
__device__ float g_v[B_*H_*S_*DH_];
__device__ float g_att[B_*S_*D_];       // [B,S,D]

// =====================================================================
// wmma fp16 split GEMM (3-pass hi/lo for fp32-grade accuracy)
// C[m][n] = sum_k A[m][k]*W[n][k] + bias[n]; M=4096, N=1024, K=1024.
// CTA tile 128x128, BK=32, 256 threads = 8 warps (2m x 4n), warp 64x32.
// MODE 0: row-major out [M][N]; MODE 1: scatter to [B,H,S,DH].
// =====================================================================
#define BKW 32
#define LDT 40          // fp16 smem leading dim (32 + 8 pad)
#define EPLD 36         // fp32 epilogue leading dim (32 + 4 pad)

// smem: operand tiles (fp16) and per-warp epilogue (fp32), unioned.
// operands: 4 tiles x 128 x LDT x 2B = 40960 B
// epilogue: 8 warps x 64 x EPLD x 4B  = 73728 B
#define GW_SMEM 73728

__device__ __forceinline__ void cvt_hilo(float x, __half& h, __half& l) {
    h = __float2half_rn(x);
    l = __float2half_rn(x - __half2float(h));
}

template<int MODE>
__global__ void __launch_bounds__(256) gemm_wmma(
    const float* __restrict__ A, const float* __restrict__ W,
    const float* __restrict__ bias, float* __restrict__ out)
{
    extern __shared__ char smem[];
    __half* sA_hi = (__half*)smem;                      // [128][LDT]
    __half* sA_lo = sA_hi + 128*LDT;
    __half* sW_hi = sA_lo + 128*LDT;
    __half* sW_lo = sW_hi + 128*LDT;
    float*  sEp   = (float*)smem;                       // epilogue union

    const int tid = threadIdx.x;
    const int wid = tid >> 5, lid = tid & 31;
    const int warp_m = wid & 1;        // 0..1 -> 64-row half
    const int warp_n = wid >> 1;       // 0..3 -> 32-col quarter
    const int m0 = blockIdx.y * 128, n0 = blockIdx.x * 128;

    // load mapping: tile 128 rows x 32 floats = 1024 float4; 4 per thread
    const int lrow = tid >> 3;         // +32 per u
    const int lc4  = tid & 7;          // float4 column

    wmma::fragment<wmma::accumulator, 16, 16, 16, float> acc[4][2];
    #pragma unroll
    for (int m = 0; m < 4; m++)
        #pragma unroll
        for (int n = 0; n < 2; n++) wmma::fill_fragment(acc[m][n], 0.0f);

    for (int kt = 0; kt < 1024/BKW; kt++) {
        const int k0 = kt * BKW;
        // prefetch to regs (overlaps previous compute)
        float4 ra[4], rw[4];
        #pragma unroll
        for (int u = 0; u < 4; u++) {
            int row = lrow + u*32;
            ra[u] = *(const float4*)&A[(size_t)(m0 + row)*1024 + k0 + lc4*4];
            rw[u] = *(const float4*)&W[(size_t)(n0 + row)*1024 + k0 + lc4*4];
        }
        __syncthreads();   // previous k-step compute done reading smem

        #pragma unroll
        for (int u = 0; u < 4; u++) {
            int row = lrow + u*32;
            int off = row*LDT + lc4*4;
            __half h0,l0,h1,l1,h2,l2,h3,l3;
            cvt_hilo(ra[u].x, h0, l0); cvt_hilo(ra[u].y, h1, l1);
            cvt_hilo(ra[u].z, h2, l2); cvt_hilo(ra[u].w, h3, l3);
            ((__half2*)&sA_hi[off])[0] = __halves2half2(h0, h1);
            ((__half2*)&sA_hi[off])[1] = __halves2half2(h2, h3);
            ((__half2*)&sA_lo[off])[0] = __halves2half2(l0, l1);
            ((__half2*)&sA_lo[off])[1] = __halves2half2(l2, l3);
            cvt_hilo(rw[u].x, h0, l0); cvt_hilo(rw[u].y, h1, l1);
            cvt_hilo(rw[u].z, h2, l2); cvt_hilo(rw[u].w, h3, l3);
            ((__half2*)&sW_hi[off])[0] = __halves2half2(h0, h1);
            ((__half2*)&sW_hi[off])[1] = __halves2half2(h2, h3);
            ((__half2*)&sW_lo[off])[0] = __halves2half2(l0, l1);
            ((__half2*)&sW_lo[off])[1] = __halves2half2(l2, l3);
        }
        __syncthreads();

        #pragma unroll
        for (int kk = 0; kk < BKW; kk += 16) {
            wmma::fragment<wmma::matrix_a, 16, 16, 16, __half, wmma::row_major> ahi[4], alo[4];
            #pragma unroll
            for (int m = 0; m < 4; m++) {
                int r = warp_m*64 + m*16;
                wmma::load_matrix_sync(ahi[m], &sA_hi[r*LDT + kk], LDT);
                wmma::load_matrix_sync(alo[m], &sA_lo[r*LDT + kk], LDT);
            }
            #pragma unroll
            for (int n = 0; n < 2; n++) {
                int c = warp_n*32 + n*16;
                wmma::fragment<wmma::matrix_b, 16, 16, 16, __half, wmma::col_major> bhi, blo;
                wmma::load_matrix_sync(bhi, &sW_hi[c*LDT + kk], LDT);
                wmma::load_matrix_sync(blo, &sW_lo[c*LDT + kk], LDT);
                #pragma unroll
                for (int m = 0; m < 4; m++) {
                    wmma::mma_sync(acc[m][n], ahi[m], bhi, acc[m][n]);
                    wmma::mma_sync(acc[m][n], ahi[m], blo, acc[m][n]);
                    wmma::mma_sync(acc[m][n], alo[m], bhi, acc[m][n]);
                }
            }
        }
    }

    // ---- epilogue: per-warp smem staging, then bias + global store ----
    __syncthreads();   // done with operand smem (union with epilogue)
    float* ep = sEp + wid * 64 * EPLD;
    #pragma unroll
    for (int m = 0; m < 4; m++)
        #pragma unroll
        for (int n = 0; n < 2; n++)
            wmma::store_matrix_sync(&ep[(m*16)*EPLD + n*16], acc[m][n],
                                    EPLD, wmma::mem_row_major);
    __syncwarp();

    const int nw0 = n0 + warp_n*32;            // warp's 32-col base
    float bv[8];
    // preload bias for the 32 cols this warp owns (each thread all 8 float4 worth? no:
    // each thread handles all 32 cols of its rows)
    #pragma unroll
    for (int c4 = 0; c4 < 8; c4++) bv[c4] = 0.f;   // placeholder (bias read per col below)

    #pragma unroll
    for (int rr = 0; rr < 2; rr++) {
        int r = lid + rr*32;                   // 0..63 within warp tile
        int gm = m0 + warp_m*64 + r;
        if (MODE == 0) {
            #pragma unroll
            for (int c4 = 0; c4 < 8; c4++) {
                float4 v = *(float4*)&ep[r*EPLD + c4*4];
                int n = nw0 + c4*4;
                v.x += bias[n+0]; v.y += bias[n+1];
                v.z += bias[n+2]; v.w += bias[n+3];
                *(float4*)&out[(size_t)gm*1024 + n] = v;
            }
        } else {
            int b = gm >> 11, s = gm & 2047;
            int h = nw0 >> 6, d0 = nw0 & 63;
            size_t base = (((size_t)(b*H_ + h))*S_ + s)*DH_ + d0;
            #pragma unroll
            for (int c4 = 0; c4 < 8; c4++) {
                float4 v = *(float4*)&ep[r*EPLD + c4*4];
                int n = nw0 + c4*4;
                v.x += bias[n+0]; v.y += bias[n+1];
                v.z += bias[n+2]; v.w += bias[n+3];
                *(float4*)&out[base + c4*4] = v;
            }
        }
    }
    (void)bv;
}

// =====================================================================
// Fused flash attention, fp32 SIMT (unchanged from R2 baseline: 1.208ms)
// =====================================================================
#define AQ 128
#define AK 128
#define QLD 132
#define PLD 129

#define OFF_QS 0
#define OFF_KS (OFF_QS + 64*QLD)
#define OFF_VS (OFF_KS + 64*QLD)
#define OFF_PS (OFF_VS + AK*DH_)
#define OFF_AL (OFF_PS + AQ*PLD)
#define OFF_LR (OFF_AL + AQ)
#define ATTN_SMEM_FLOATS (OFF_LR + AQ)
#define ATTN_SMEM_BYTES (ATTN_SMEM_FLOATS * 4)

__global__ void __launch_bounds__(256, 1) attn_kernel()
{
    extern __shared__ float sm[];
    float* Qs = sm + OFF_QS;
    float* Ks = sm + OFF_KS;
    float* Vs = sm + OFF_VS;
    float* Ps = sm + OFF_PS;
    float* alphas = sm + OFF_AL;
    float* lrow = sm + OFF_LR;

    const int tid = threadIdx.x;
    const int tx = tid & 15, ty = tid >> 4;
    const int tn2 = tid & 7, tm2 = tid >> 3;
    const int bh = blockIdx.y;
    const int q0 = blockIdx.x * AQ;

    const float* qbase = g_q + (size_t)bh*S_*DH_;
    const float* kbase = g_k + (size_t)bh*S_*DH_;
    const float* vbase = g_v + (size_t)bh*S_*DH_;

    #pragma unroll
    for (int u = 0; u < 8; u++) {
        int idx = u*256 + tid;
        int r = idx >> 4, c4 = idx & 15;
        float4 qv = *(const float4*)&qbase[(size_t)(q0 + r)*DH_ + c4*4];
        Qs[(c4*4+0)*QLD + r] = qv.x;
        Qs[(c4*4+1)*QLD + r] = qv.y;
        Qs[(c4*4+2)*QLD + r] = qv.z;
        Qs[(c4*4+3)*QLD + r] = qv.w;
    }

    float mrow[8], lacc[8];
    float o[4][8];
    #pragma unroll
    for (int i = 0; i < 8; i++) { mrow[i] = -INFINITY; lacc[i] = 0.f; }
    #pragma unroll
    for (int i = 0; i < 4; i++)
        #pragma unroll
        for (int j = 0; j < 8; j++) o[i][j] = 0.f;

    for (int kt = 0; kt < S_/AK; kt++) {
        __syncthreads();
        const int k0 = kt*AK;
        #pragma unroll
        for (int u = 0; u < 8; u++) {
            int idx = u*256 + tid;
            int r = idx >> 4, c4 = idx & 15;
            float4 kv = *(const float4*)&kbase[(size_t)(k0 + r)*DH_ + c4*4];
            Ks[(c4*4+0)*QLD + r] = kv.x;
            Ks[(c4*4+1)*QLD + r] = kv.y;
            Ks[(c4*4+2)*QLD + r] = kv.z;
            Ks[(c4*4+3)*QLD + r] = kv.w;
            float4 vv = *(const float4*)&vbase[(size_t)(k0 + r)*DH_ + c4*4];
            *(float4*)&Vs[r*DH_ + c4*4] = vv;
        }
        __syncthreads();

        float s[8][8];
        #pragma unroll
        for (int i = 0; i < 8; i++)
            #pragma unroll
            for (int j = 0; j < 8; j++) s[i][j] = 0.f;

        #pragma unroll 16
        for (int d = 0; d < DH_; d++) {
            float a[8], b[8];
            *(float4*)&a[0] = *(const float4*)&Qs[d*QLD + ty*8];
            *(float4*)&a[4] = *(const float4*)&Qs[d*QLD + ty*8 + 4];
            *(float4*)&b[0] = *(const float4*)&Ks[d*QLD + tx*8];
            *(float4*)&b[4] = *(const float4*)&Ks[d*QLD + tx*8 + 4];
            #pragma unroll
            for (int i = 0; i < 8; i++)
                #pragma unroll
                for (int j = 0; j < 8; j++)
                    s[i][j] += a[i]*b[j];
        }

        #pragma unroll
        for (int i = 0; i < 8; i++) {
            #pragma unroll
            for (int j = 0; j < 8; j++) s[i][j] *= 0.125f;
            float mx = s[i][0];
            #pragma unroll
            for (int j = 1; j < 8; j++) mx = fmaxf(mx, s[i][j]);
            #pragma unroll
            for (int off = 8; off >= 1; off >>= 1)
                mx = fmaxf(mx, __shfl_xor_sync(0xffffffffu, mx, off));
            float mnew = fmaxf(mrow[i], mx);
            float alpha = __expf(mrow[i] - mnew);
            mrow[i] = mnew;
            float sum = 0.f;
            #pragma unroll
            for (int j = 0; j < 8; j++) {
                s[i][j] = __expf(s[i][j] - mnew);
                sum += s[i][j];
            }
            #pragma unroll
            for (int off = 8; off >= 1; off >>= 1)
                sum += __shfl_xor_sync(0xffffffffu, sum, off);
            lacc[i] = lacc[i]*alpha + sum;

            int r = ty*8 + i;
            #pragma unroll
            for (int j = 0; j < 8; j++) Ps[r*PLD + tx*8 + j] = s[i][j];
            if (tx == 0) { alphas[r] = alpha; lrow[r] = lacc[i]; }
        }
        __syncthreads();

        float al[4];
        #pragma unroll
        for (int i = 0; i < 4; i++) al[i] = alphas[tm2*4 + i];
        #pragma unroll
        for (int i = 0; i < 4; i++)
            #pragma unroll
            for (int j = 0; j < 8; j++) o[i][j] *= al[i];

        #pragma unroll 16
        for (int j = 0; j < AK; j++) {
            float p[4];
            #pragma unroll
            for (int i = 0; i < 4; i++) p[i] = Ps[(tm2*4 + i)*PLD + j];
            float vv[8];
            *(float4*)&vv[0] = *(const float4*)&Vs[j*DH_ + tn2*8];
            *(float4*)&vv[4] = *(const float4*)&Vs[j*DH_ + tn2*8 + 4];
            #pragma unroll
            for (int i = 0; i < 4; i++)
                #pragma unroll
                for (int jj = 0; jj < 8; jj++)
                    o[i][jj] += p[i]*vv[jj];
        }
    }

    const int b = bh >> 4, h = bh & 15;
    #pragma unroll
    for (int i = 0; i < 4; i++) {
        int m = tm2*4 + i;
        float linv = 1.0f / lrow[m];
        float4 r0, r1;
        r0.x = o[i][0]*linv; r0.y = o[i][1]*linv;
        r0.z = o[i][2]*linv; r0.w = o[i][3]*linv;
        r1.x = o[i][4]*linv; r1.y = o[i][5]*linv;
        r1.z = o[i][6]*linv; r1.w = o[i][7]*linv;
        size_t off = ((size_t)(b*S_ + q0 + m))*D_ + h*DH_ + tn2*8;
        *(float4*)&g_att[off]     = r0;
        *(float4*)&g_att[off + 4] = r1;
    }
}

// =====================================================================
// Launch
// =====================================================================
extern "C" void kernel_launch(void* const* d_in, const int* in_sizes, int n_in,
                              void* d_out, int out_size)
{
    const float* query  = (const float*)d_in[0];
    const float* keys   = (const float*)d_in[1];
    const float* values = (const float*)d_in[2];
    const float* Wq = (const float*)d_in[3];
    const float* bq = (const float*)d_in[4];
    const float* Wk = (const float*)d_in[5];
    const float* bk = (const float*)d_in[6];
    const float* Wv = (const float*)d_in[7];
    const float* bv = (const float*)d_in[8];
    const float* Wo = (const float*)d_in[9];
    const float* bo = (const float*)d_in[10];
    float* out = (float*)d_out;

    float *qp, *kp, *vp, *ap;
    cudaGetSymbolAddress((void**)&qp, g_q);
    cudaGetSymbolAddress((void**)&kp, g_k);
    cudaGetSymbolAddress((void**)&vp, g_v);
    cudaGetSymbolAddress((void**)&ap, g_att);

    cudaFuncSetAttribute(gemm_wmma<0>,
                         cudaFuncAttributeMaxDynamicSharedMemorySize, GW_SMEM);
    cudaFuncSetAttribute(gemm_wmma<1>,
                         cudaFuncAttributeMaxDynamicSharedMemorySize, GW_SMEM);
    cudaFuncSetAttribute(attn_kernel,
                         cudaFuncAttributeMaxDynamicSharedMemorySize,
                         ATTN_SMEM_BYTES);

    dim3 gemm_grid(D_/128, M_/128);   // (8, 32)
    gemm_wmma<1><<<gemm_grid, 256, GW_SMEM>>>(query,  Wq, bq, qp);
    gemm_wmma<1><<<gemm_grid, 256, GW_SMEM>>>(keys,   Wk, bk, kp);
    gemm_wmma<1><<<gemm_grid, 256, GW_SMEM>>>(values, Wv, bv, vp);

    attn_kernel<<<dim3(S_/AQ, B_*H_), 256, ATTN_SMEM_BYTES>>>();

    gemm_wmma<0><<<gemm_grid, 256, GW_SMEM>>>(ap, Wo, bo, out);
}

// round 7
// speedup vs baseline: 2.4470x; 1.8915x over previous
#include <cuda_runtime.h>
#include <cuda_fp16.h>
#include <mma.h>
#include <math.h>
#include <stdint.h>

using namespace nvcuda;

// Problem constants
#define B_   2
#define S_   2048
#define D_   1024
#define H_   16
#define DH_  64
#define M_   (B_*S_)          // 4096 rows for all projections

// ---------------- scratch (device globals; no allocation) ----------------
__device__ float g_q[B_*H_*S_*DH_];     // [B,H,S,DH]
__device__ float g_k[B_*H_*S_*DH_];
__device__ float g_v[B_*H_*S_*DH_];
__device__ float g_att[B_*S_*D_];       // [B,S,D]

__device__ __forceinline__ void cvt_hilo(float x, __half& h, __half& l) {
    h = __float2half_rn(x);
    l = __float2half_rn(x - __half2float(h));
}

// =====================================================================
// wmma fp16 split GEMM (3-pass hi/lo) — unchanged from R5 (validated)
// =====================================================================
#define BKW 32
#define LDT 40
#define EPLD 36
#define GW_SMEM 73728

template<int MODE>
__global__ void __launch_bounds__(256) gemm_wmma(
    const float* __restrict__ A, const float* __restrict__ W,
    const float* __restrict__ bias, float* __restrict__ out)
{
    extern __shared__ char smem[];
    __half* sA_hi = (__half*)smem;
    __half* sA_lo = sA_hi + 128*LDT;
    __half* sW_hi = sA_lo + 128*LDT;
    __half* sW_lo = sW_hi + 128*LDT;
    float*  sEp   = (float*)smem;

    const int tid = threadIdx.x;
    const int wid = tid >> 5, lid = tid & 31;
    const int warp_m = wid & 1;
    const int warp_n = wid >> 1;
    const int m0 = blockIdx.y * 128, n0 = blockIdx.x * 128;

    const int lrow = tid >> 3;
    const int lc4  = tid & 7;

    wmma::fragment<wmma::accumulator, 16, 16, 16, float> acc[4][2];
    #pragma unroll
    for (int m = 0; m < 4; m++)
        #pragma unroll
        for (int n = 0; n < 2; n++) wmma::fill_fragment(acc[m][n], 0.0f);

    for (int kt = 0; kt < 1024/BKW; kt++) {
        const int k0 = kt * BKW;
        float4 ra[4], rw[4];
        #pragma unroll
        for (int u = 0; u < 4; u++) {
            int row = lrow + u*32;
            ra[u] = *(const float4*)&A[(size_t)(m0 + row)*1024 + k0 + lc4*4];
            rw[u] = *(const float4*)&W[(size_t)(n0 + row)*1024 + k0 + lc4*4];
        }
        __syncthreads();

        #pragma unroll
        for (int u = 0; u < 4; u++) {
            int row = lrow + u*32;
            int off = row*LDT + lc4*4;
            __half h0,l0,h1,l1,h2,l2,h3,l3;
            cvt_hilo(ra[u].x, h0, l0); cvt_hilo(ra[u].y, h1, l1);
            cvt_hilo(ra[u].z, h2, l2); cvt_hilo(ra[u].w, h3, l3);
            ((__half2*)&sA_hi[off])[0] = __halves2half2(h0, h1);
            ((__half2*)&sA_hi[off])[1] = __halves2half2(h2, h3);
            ((__half2*)&sA_lo[off])[0] = __halves2half2(l0, l1);
            ((__half2*)&sA_lo[off])[1] = __halves2half2(l2, l3);
            cvt_hilo(rw[u].x, h0, l0); cvt_hilo(rw[u].y, h1, l1);
            cvt_hilo(rw[u].z, h2, l2); cvt_hilo(rw[u].w, h3, l3);
            ((__half2*)&sW_hi[off])[0] = __halves2half2(h0, h1);
            ((__half2*)&sW_hi[off])[1] = __halves2half2(h2, h3);
            ((__half2*)&sW_lo[off])[0] = __halves2half2(l0, l1);
            ((__half2*)&sW_lo[off])[1] = __halves2half2(l2, l3);
        }
        __syncthreads();

        #pragma unroll
        for (int kk = 0; kk < BKW; kk += 16) {
            wmma::fragment<wmma::matrix_a, 16, 16, 16, __half, wmma::row_major> ahi[4], alo[4];
            #pragma unroll
            for (int m = 0; m < 4; m++) {
                int r = warp_m*64 + m*16;
                wmma::load_matrix_sync(ahi[m], &sA_hi[r*LDT + kk], LDT);
                wmma::load_matrix_sync(alo[m], &sA_lo[r*LDT + kk], LDT);
            }
            #pragma unroll
            for (int n = 0; n < 2; n++) {
                int c = warp_n*32 + n*16;
                wmma::fragment<wmma::matrix_b, 16, 16, 16, __half, wmma::col_major> bhi, blo;
                wmma::load_matrix_sync(bhi, &sW_hi[c*LDT + kk], LDT);
                wmma::load_matrix_sync(blo, &sW_lo[c*LDT + kk], LDT);
                #pragma unroll
                for (int m = 0; m < 4; m++) {
                    wmma::mma_sync(acc[m][n], ahi[m], bhi, acc[m][n]);
                    wmma::mma_sync(acc[m][n], ahi[m], blo, acc[m][n]);
                    wmma::mma_sync(acc[m][n], alo[m], bhi, acc[m][n]);
                }
            }
        }
    }

    __syncthreads();
    float* ep = sEp + wid * 64 * EPLD;
    #pragma unroll
    for (int m = 0; m < 4; m++)
        #pragma unroll
        for (int n = 0; n < 2; n++)
            wmma::store_matrix_sync(&ep[(m*16)*EPLD + n*16], acc[m][n],
                                    EPLD, wmma::mem_row_major);
    __syncwarp();

    const int nw0 = n0 + warp_n*32;
    #pragma unroll
    for (int rr = 0; rr < 2; rr++) {
        int r = lid + rr*32;
        int gm = m0 + warp_m*64 + r;
        if (MODE == 0) {
            #pragma unroll
            for (int c4 = 0; c4 < 8; c4++) {
                float4 v = *(float4*)&ep[r*EPLD + c4*4];
                int n = nw0 + c4*4;
                v.x += bias[n+0]; v.y += bias[n+1];
                v.z += bias[n+2]; v.w += bias[n+3];
                *(float4*)&out[(size_t)gm*1024 + n] = v;
            }
        } else {
            int b = gm >> 11, s = gm & 2047;
            int h = nw0 >> 6, d0 = nw0 & 63;
            size_t base = (((size_t)(b*H_ + h))*S_ + s)*DH_ + d0;
            #pragma unroll
            for (int c4 = 0; c4 < 8; c4++) {
                float4 v = *(float4*)&ep[r*EPLD + c4*4];
                int n = nw0 + c4*4;
                v.x += bias[n+0]; v.y += bias[n+1];
                v.z += bias[n+2]; v.w += bias[n+3];
                *(float4*)&out[base + c4*4] = v;
            }
        }
    }
}

// =====================================================================
// wmma flash attention.
// One CTA = (b,h) x 128-query tile. 256 threads / 8 warps.
// QK^T: 3-pass hi/lo split (fp32-grade scores).
// PV:   P fp16 single, V hi/lo 2-pass.
// O kept in registers (32 floats/thread); PV result staged via smem
// (aliases the dead K buffer) to avoid fragment-layout assumptions.
// =====================================================================
#define TLD 72          // half LD for Q/K/V tiles (64 + 8 pad)
#define SLD 132         // fp32 LD for S (128 + 4 pad)
#define PLD2 136        // half LD for P (128 + 8 pad)
#define STLD 68         // fp32 LD for PV staging (64 + 4 pad)

// smem byte layout
#define AT_QHI 0
#define AT_QLO (AT_QHI + 128*TLD*2)
#define AT_KHI (AT_QLO + 128*TLD*2)
#define AT_KLO (AT_KHI + 128*TLD*2)
#define AT_VHI (AT_KLO + 128*TLD*2)
#define AT_VLO (AT_VHI + 128*TLD*2)
#define AT_S   (AT_VLO + 128*TLD*2)            // 110592
#define AT_P   (AT_S + 128*SLD*4)              // 178176
#define AT_M   (AT_P + 128*PLD2*2)             // 212992
#define AT_L   (AT_M + 128*4)
#define AT_A   (AT_L + 128*4)
#define ATT_SMEM (AT_A + 128*4)                // 214528

__global__ void __launch_bounds__(256, 1) attn_wmma()
{
    extern __shared__ char smem[];
    __half* Qhi = (__half*)(smem + AT_QHI);
    __half* Qlo = (__half*)(smem + AT_QLO);
    __half* Khi = (__half*)(smem + AT_KHI);
    __half* Klo = (__half*)(smem + AT_KLO);
    __half* Vhi = (__half*)(smem + AT_VHI);
    __half* Vlo = (__half*)(smem + AT_VLO);
    float*  Sb  = (float*)(smem + AT_S);
    __half* Pb  = (__half*)(smem + AT_P);
    float*  mrow = (float*)(smem + AT_M);
    float*  lrow = (float*)(smem + AT_L);
    float*  arow = (float*)(smem + AT_A);
    float*  stage = (float*)(smem + AT_KHI);   // alias: K dead when staged

    const int tid = threadIdx.x;
    const int wid = tid >> 5;
    const int warp_m = wid & 1;      // 0..1  (64-row half)
    const int warp_n = wid >> 1;     // 0..3
    const int bh = blockIdx.y;
    const int q0 = blockIdx.x * 128;

    const float* qbase = g_q + (size_t)bh*S_*DH_;
    const float* kbase = g_k + (size_t)bh*S_*DH_;
    const float* vbase = g_v + (size_t)bh*S_*DH_;

    // ---- load Q tile once (128x64 fp32 -> hi/lo fp16) ----
    #pragma unroll
    for (int u = 0; u < 8; u++) {
        int idx = u*256 + tid;
        int r = idx >> 4, c4 = idx & 15;
        float4 qv = *(const float4*)&qbase[(size_t)(q0 + r)*DH_ + c4*4];
        int off = r*TLD + c4*4;
        __half h0,l0,h1,l1,h2,l2,h3,l3;
        cvt_hilo(qv.x, h0, l0); cvt_hilo(qv.y, h1, l1);
        cvt_hilo(qv.z, h2, l2); cvt_hilo(qv.w, h3, l3);
        ((__half2*)&Qhi[off])[0] = __halves2half2(h0, h1);
        ((__half2*)&Qhi[off])[1] = __halves2half2(h2, h3);
        ((__half2*)&Qlo[off])[0] = __halves2half2(l0, l1);
        ((__half2*)&Qlo[off])[1] = __halves2half2(l2, l3);
    }
    if (tid < 128) { mrow[tid] = -INFINITY; lrow[tid] = 0.f; }

    const int orow = tid >> 1;              // O mapping: row, 32-col half
    const int oc0  = (tid & 1) * 32;
    float O[32];
    #pragma unroll
    for (int i = 0; i < 32; i++) O[i] = 0.f;

    for (int kt = 0; kt < S_/128; kt++) {
        __syncthreads();                 // (a) stage consumed, Q/m/l visible
        const int k0 = kt * 128;
        // ---- load K,V tile (hi/lo) ----
        #pragma unroll
        for (int u = 0; u < 8; u++) {
            int idx = u*256 + tid;
            int r = idx >> 4, c4 = idx & 15;
            int off = r*TLD + c4*4;
            float4 kv = *(const float4*)&kbase[(size_t)(k0 + r)*DH_ + c4*4];
            __half h0,l0,h1,l1,h2,l2,h3,l3;
            cvt_hilo(kv.x, h0, l0); cvt_hilo(kv.y, h1, l1);
            cvt_hilo(kv.z, h2, l2); cvt_hilo(kv.w, h3, l3);
            ((__half2*)&Khi[off])[0] = __halves2half2(h0, h1);
            ((__half2*)&Khi[off])[1] = __halves2half2(h2, h3);
            ((__half2*)&Klo[off])[0] = __halves2half2(l0, l1);
            ((__half2*)&Klo[off])[1] = __halves2half2(l2, l3);
            float4 vv = *(const float4*)&vbase[(size_t)(k0 + r)*DH_ + c4*4];
            cvt_hilo(vv.x, h0, l0); cvt_hilo(vv.y, h1, l1);
            cvt_hilo(vv.z, h2, l2); cvt_hilo(vv.w, h3, l3);
            ((__half2*)&Vhi[off])[0] = __halves2half2(h0, h1);
            ((__half2*)&Vhi[off])[1] = __halves2half2(h2, h3);
            ((__half2*)&Vlo[off])[0] = __halves2half2(l0, l1);
            ((__half2*)&Vlo[off])[1] = __halves2half2(l2, l3);
        }
        __syncthreads();                 // (b) K,V ready

        // ---- S = Q K^T (3-pass), warp tile 64x32 ----
        {
            wmma::fragment<wmma::accumulator, 16, 16, 16, float> sfr[4][2];
            #pragma unroll
            for (int m = 0; m < 4; m++)
                #pragma unroll
                for (int n = 0; n < 2; n++) wmma::fill_fragment(sfr[m][n], 0.0f);

            #pragma unroll
            for (int kk = 0; kk < 64; kk += 16) {
                wmma::fragment<wmma::matrix_a, 16, 16, 16, __half, wmma::row_major> qh[4], ql[4];
                #pragma unroll
                for (int m = 0; m < 4; m++) {
                    int r = warp_m*64 + m*16;
                    wmma::load_matrix_sync(qh[m], &Qhi[r*TLD + kk], TLD);
                    wmma::load_matrix_sync(ql[m], &Qlo[r*TLD + kk], TLD);
                }
                #pragma unroll
                for (int n = 0; n < 2; n++) {
                    int c = warp_n*32 + n*16;
                    wmma::fragment<wmma::matrix_b, 16, 16, 16, __half, wmma::col_major> kh, kl;
                    wmma::load_matrix_sync(kh, &Khi[c*TLD + kk], TLD);
                    wmma::load_matrix_sync(kl, &Klo[c*TLD + kk], TLD);
                    #pragma unroll
                    for (int m = 0; m < 4; m++) {
                        wmma::mma_sync(sfr[m][n], qh[m], kh, sfr[m][n]);
                        wmma::mma_sync(sfr[m][n], qh[m], kl, sfr[m][n]);
                        wmma::mma_sync(sfr[m][n], ql[m], kh, sfr[m][n]);
                    }
                }
            }
            #pragma unroll
            for (int m = 0; m < 4; m++)
                #pragma unroll
                for (int n = 0; n < 2; n++)
                    wmma::store_matrix_sync(
                        &Sb[(warp_m*64 + m*16)*SLD + warp_n*32 + n*16],
                        sfr[m][n], SLD, wmma::mem_row_major);
        }
        __syncthreads();                 // (c) S ready

        // ---- online softmax: 2 threads per row ----
        {
            const int r = tid >> 1, h = tid & 1;
            const float* srow = Sb + r*SLD + h*64;
            float sv[64];
            float mx = -INFINITY;
            #pragma unroll
            for (int i = 0; i < 16; i++) {
                float4 v = *(const float4*)&srow[i*4];
                sv[i*4+0] = v.x * 0.125f; sv[i*4+1] = v.y * 0.125f;
                sv[i*4+2] = v.z * 0.125f; sv[i*4+3] = v.w * 0.125f;
            }
            #pragma unroll
            for (int i = 0; i < 64; i++) mx = fmaxf(mx, sv[i]);
            mx = fmaxf(mx, __shfl_xor_sync(0xffffffffu, mx, 1));
            float mold = mrow[r];
            float mnew = fmaxf(mold, mx);
            float alpha = __expf(mold - mnew);
            float sum = 0.f;
            __half* prow = Pb + r*PLD2 + h*64;
            #pragma unroll
            for (int i = 0; i < 32; i++) {
                float p0 = __expf(sv[i*2+0] - mnew);
                float p1 = __expf(sv[i*2+1] - mnew);
                sum += p0 + p1;
                ((__half2*)prow)[i] = __halves2half2(__float2half_rn(p0),
                                                     __float2half_rn(p1));
            }
            sum += __shfl_xor_sync(0xffffffffu, sum, 1);
            if (h == 0) {
                mrow[r] = mnew;
                lrow[r] = lrow[r]*alpha + sum;
                arow[r] = alpha;
            }
        }
        __syncthreads();                 // (d) P, alpha ready

        // ---- PV (P single, V 2-pass), warp tile 64x16 ----
        {
            wmma::fragment<wmma::accumulator, 16, 16, 16, float> pv[4];
            #pragma unroll
            for (int m = 0; m < 4; m++) wmma::fill_fragment(pv[m], 0.0f);
            #pragma unroll
            for (int j0 = 0; j0 < 128; j0 += 16) {
                wmma::fragment<wmma::matrix_a, 16, 16, 16, __half, wmma::row_major> pf[4];
                #pragma unroll
                for (int m = 0; m < 4; m++)
                    wmma::load_matrix_sync(pf[m],
                        &Pb[(warp_m*64 + m*16)*PLD2 + j0], PLD2);
                wmma::fragment<wmma::matrix_b, 16, 16, 16, __half, wmma::row_major> vh, vl;
                wmma::load_matrix_sync(vh, &Vhi[j0*TLD + warp_n*16], TLD);
                wmma::load_matrix_sync(vl, &Vlo[j0*TLD + warp_n*16], TLD);
                #pragma unroll
                for (int m = 0; m < 4; m++) {
                    wmma::mma_sync(pv[m], pf[m], vh, pv[m]);
                    wmma::mma_sync(pv[m], pf[m], vl, pv[m]);
                }
            }
            #pragma unroll
            for (int m = 0; m < 4; m++)
                wmma::store_matrix_sync(
                    &stage[(warp_m*64 + m*16)*STLD + warp_n*16],
                    pv[m], STLD, wmma::mem_row_major);
        }
        __syncthreads();                 // (e) stage ready

        // ---- O = O*alpha + stage ----
        {
            float alpha = arow[orow];
            const float* st = stage + orow*STLD + oc0;
            #pragma unroll
            for (int i = 0; i < 8; i++) {
                float4 v = *(const float4*)&st[i*4];
                O[i*4+0] = O[i*4+0]*alpha + v.x;
                O[i*4+1] = O[i*4+1]*alpha + v.y;
                O[i*4+2] = O[i*4+2]*alpha + v.z;
                O[i*4+3] = O[i*4+3]*alpha + v.w;
            }
        }
    }

    // ---- normalize + write [B,S,D] ----
    __syncthreads();
    const int b = bh >> 4, h = bh & 15;
    float linv = 1.0f / lrow[orow];
    size_t base = ((size_t)(b*S_ + q0 + orow))*D_ + h*DH_ + oc0;
    #pragma unroll
    for (int i = 0; i < 8; i++) {
        float4 v;
        v.x = O[i*4+0]*linv; v.y = O[i*4+1]*linv;
        v.z = O[i*4+2]*linv; v.w = O[i*4+3]*linv;
        *(float4*)&g_att[base + i*4] = v;
    }
}

// =====================================================================
// Launch
// =====================================================================
extern "C" void kernel_launch(void* const* d_in, const int* in_sizes, int n_in,
                              void* d_out, int out_size)
{
    const float* query  = (const float*)d_in[0];
    const float* keys   = (const float*)d_in[1];
    const float* values = (const float*)d_in[2];
    const float* Wq = (const float*)d_in[3];
    const float* bq = (const float*)d_in[4];
    const float* Wk = (const float*)d_in[5];
    const float* bk = (const float*)d_in[6];
    const float* Wv = (const float*)d_in[7];
    const float* bv = (const float*)d_in[8];
    const float* Wo = (const float*)d_in[9];
    const float* bo = (const float*)d_in[10];
    float* out = (float*)d_out;

    float *qp, *kp, *vp, *ap;
    cudaGetSymbolAddress((void**)&qp, g_q);
    cudaGetSymbolAddress((void**)&kp, g_k);
    cudaGetSymbolAddress((void**)&vp, g_v);
    cudaGetSymbolAddress((void**)&ap, g_att);

    cudaFuncSetAttribute(gemm_wmma<0>,
                         cudaFuncAttributeMaxDynamicSharedMemorySize, GW_SMEM);
    cudaFuncSetAttribute(gemm_wmma<1>,
                         cudaFuncAttributeMaxDynamicSharedMemorySize, GW_SMEM);
    cudaFuncSetAttribute(attn_wmma,
                         cudaFuncAttributeMaxDynamicSharedMemorySize, ATT_SMEM);

    dim3 gemm_grid(D_/128, M_/128);   // (8, 32)
    gemm_wmma<1><<<gemm_grid, 256, GW_SMEM>>>(query,  Wq, bq, qp);
    gemm_wmma<1><<<gemm_grid, 256, GW_SMEM>>>(keys,   Wk, bk, kp);
    gemm_wmma<1><<<gemm_grid, 256, GW_SMEM>>>(values, Wv, bv, vp);

    attn_wmma<<<dim3(S_/128, B_*H_), 256, ATT_SMEM>>>();

    gemm_wmma<0><<<gemm_grid, 256, GW_SMEM>>>(ap, Wo, bo, out);
}

// round 9
// speedup vs baseline: 2.5038x; 1.0232x over previous
#include <cuda_runtime.h>
#include <cuda_fp16.h>
#include <mma.h>
#include <math.h>
#include <stdint.h>

using namespace nvcuda;

// Problem constants
#define B_   2
#define S_   2048
#define D_   1024
#define H_   16
#define DH_  64
#define M_   (B_*S_)

// ---------------- scratch (device globals; no allocation) ----------------
__device__ float g_q[B_*H_*S_*DH_];     // [B,H,S,DH]
__device__ float g_k[B_*H_*S_*DH_];
__device__ float g_v[B_*H_*S_*DH_];
__device__ float g_att[B_*S_*D_];       // [B,S,D]

__device__ __forceinline__ void cvt_hilo(float x, __half& h, __half& l) {
    h = __float2half_rn(x);
    l = __float2half_rn(x - __half2float(h));
}

__device__ __forceinline__ uint32_t h2_to_u32(__half2 h) {
    union { __half2 h2; uint32_t u; } cv;
    cv.h2 = h;
    return cv.u;
}

// m16n8k16 fp16 MMA, fp32 accumulate (HMMA.16816)
__device__ __forceinline__ void mma16816(float* d, const uint32_t* a, const uint32_t* b) {
    asm volatile(
        "mma.sync.aligned.m16n8k16.row.col.f32.f16.f16.f32 "
        "{%0,%1,%2,%3}, {%4,%5,%6,%7}, {%8,%9}, {%0,%1,%2,%3};\n"
        : "+f"(d[0]), "+f"(d[1]), "+f"(d[2]), "+f"(d[3])
        : "r"(a[0]), "r"(a[1]), "r"(a[2]), "r"(a[3]), "r"(b[0]), "r"(b[1]));
}

// =====================================================================
// wmma fp16 split GEMM (3-pass hi/lo) — unchanged from R5/R7 (validated)
// =====================================================================
#define BKW 32
#define LDT 40
#define EPLD 36
#define GW_SMEM 73728

template<int MODE>
__global__ void __launch_bounds__(256) gemm_wmma(
    const float* __restrict__ A, const float* __restrict__ W,
    const float* __restrict__ bias, float* __restrict__ out)
{
    extern __shared__ char smem[];
    __half* sA_hi = (__half*)smem;
    __half* sA_lo = sA_hi + 128*LDT;
    __half* sW_hi = sA_lo + 128*LDT;
    __half* sW_lo = sW_hi + 128*LDT;
    float*  sEp   = (float*)smem;

    const int tid = threadIdx.x;
    const int wid = tid >> 5, lid = tid & 31;
    const int warp_m = wid & 1;
    const int warp_n = wid >> 1;
    const int m0 = blockIdx.y * 128, n0 = blockIdx.x * 128;

    const int lrow = tid >> 3;
    const int lc4  = tid & 7;

    wmma::fragment<wmma::accumulator, 16, 16, 16, float> acc[4][2];
    #pragma unroll
    for (int m = 0; m < 4; m++)
        #pragma unroll
        for (int n = 0; n < 2; n++) wmma::fill_fragment(acc[m][n], 0.0f);

    for (int kt = 0; kt < 1024/BKW; kt++) {
        const int k0 = kt * BKW;
        float4 ra[4], rw[4];
        #pragma unroll
        for (int u = 0; u < 4; u++) {
            int row = lrow + u*32;
            ra[u] = *(const float4*)&A[(size_t)(m0 + row)*1024 + k0 + lc4*4];
            rw[u] = *(const float4*)&W[(size_t)(n0 + row)*1024 + k0 + lc4*4];
        }
        __syncthreads();

        #pragma unroll
        for (int u = 0; u < 4; u++) {
            int row = lrow + u*32;
            int off = row*LDT + lc4*4;
            __half h0,l0,h1,l1,h2,l2,h3,l3;
            cvt_hilo(ra[u].x, h0, l0); cvt_hilo(ra[u].y, h1, l1);
            cvt_hilo(ra[u].z, h2, l2); cvt_hilo(ra[u].w, h3, l3);
            ((__half2*)&sA_hi[off])[0] = __halves2half2(h0, h1);
            ((__half2*)&sA_hi[off])[1] = __halves2half2(h2, h3);
            ((__half2*)&sA_lo[off])[0] = __halves2half2(l0, l1);
            ((__half2*)&sA_lo[off])[1] = __halves2half2(l2, l3);
            cvt_hilo(rw[u].x, h0, l0); cvt_hilo(rw[u].y, h1, l1);
            cvt_hilo(rw[u].z, h2, l2); cvt_hilo(rw[u].w, h3, l3);
            ((__half2*)&sW_hi[off])[0] = __halves2half2(h0, h1);
            ((__half2*)&sW_hi[off])[1] = __halves2half2(h2, h3);
            ((__half2*)&sW_lo[off])[0] = __halves2half2(l0, l1);
            ((__half2*)&sW_lo[off])[1] = __halves2half2(l2, l3);
        }
        __syncthreads();

        #pragma unroll
        for (int kk = 0; kk < BKW; kk += 16) {
            wmma::fragment<wmma::matrix_a, 16, 16, 16, __half, wmma::row_major> ahi[4], alo[4];
            #pragma unroll
            for (int m = 0; m < 4; m++) {
                int r = warp_m*64 + m*16;
                wmma::load_matrix_sync(ahi[m], &sA_hi[r*LDT + kk], LDT);
                wmma::load_matrix_sync(alo[m], &sA_lo[r*LDT + kk], LDT);
            }
            #pragma unroll
            for (int n = 0; n < 2; n++) {
                int c = warp_n*32 + n*16;
                wmma::fragment<wmma::matrix_b, 16, 16, 16, __half, wmma::col_major> bhi, blo;
                wmma::load_matrix_sync(bhi, &sW_hi[c*LDT + kk], LDT);
                wmma::load_matrix_sync(blo, &sW_lo[c*LDT + kk], LDT);
                #pragma unroll
                for (int m = 0; m < 4; m++) {
                    wmma::mma_sync(acc[m][n], ahi[m], bhi, acc[m][n]);
                    wmma::mma_sync(acc[m][n], ahi[m], blo, acc[m][n]);
                    wmma::mma_sync(acc[m][n], alo[m], bhi, acc[m][n]);
                }
            }
        }
    }

    __syncthreads();
    float* ep = sEp + wid * 64 * EPLD;
    #pragma unroll
    for (int m = 0; m < 4; m++)
        #pragma unroll
        for (int n = 0; n < 2; n++)
            wmma::store_matrix_sync(&ep[(m*16)*EPLD + n*16], acc[m][n],
                                    EPLD, wmma::mem_row_major);
    __syncwarp();

    const int nw0 = n0 + warp_n*32;
    #pragma unroll
    for (int rr = 0; rr < 2; rr++) {
        int r = lid + rr*32;
        int gm = m0 + warp_m*64 + r;
        if (MODE == 0) {
            #pragma unroll
            for (int c4 = 0; c4 < 8; c4++) {
                float4 v = *(float4*)&ep[r*EPLD + c4*4];
                int n = nw0 + c4*4;
                v.x += bias[n+0]; v.y += bias[n+1];
                v.z += bias[n+2]; v.w += bias[n+3];
                *(float4*)&out[(size_t)gm*1024 + n] = v;
            }
        } else {
            int b = gm >> 11, s = gm & 2047;
            int h = nw0 >> 6, d0 = nw0 & 63;
            size_t base = (((size_t)(b*H_ + h))*S_ + s)*DH_ + d0;
            #pragma unroll
            for (int c4 = 0; c4 < 8; c4++) {
                float4 v = *(float4*)&ep[r*EPLD + c4*4];
                int n = nw0 + c4*4;
                v.x += bias[n+0]; v.y += bias[n+1];
                v.z += bias[n+2]; v.w += bias[n+3];
                *(float4*)&out[base + c4*4] = v;
            }
        }
    }
}

// =====================================================================
// Flash attention on raw mma.sync m16n8k16 — fully register-resident
// S / softmax / P / O. One CTA = (b,h) x 128 q-rows, 8 warps x 16 rows.
// QK^T: 3-pass hi/lo. PV: P single fp16, V 2-pass hi/lo.
// smem: Q,K hi/lo [128][TLD]; V transposed hi/lo [64][VLD2].
// 2 __syncthreads per key tile.
// =====================================================================
#define TLD 72          // Q/K leading dim (halves): fragment LDS conflict-free
#define VLD2 136        // Vt leading dim (halves): bank = 4g + c -> conflict-free

#define AT_QHI 0
#define AT_QLO (AT_QHI + 128*TLD*2)      // 18432
#define AT_KHI (AT_QLO + 128*TLD*2)      // 36864
#define AT_KLO (AT_KHI + 128*TLD*2)      // 55296
#define AT_VHI (AT_KLO + 128*TLD*2)      // 73728
#define AT_VLO (AT_VHI + 64*VLD2*2)      // 91136
#define ATT_SMEM (AT_VLO + 64*VLD2*2)    // 108544

__global__ void __launch_bounds__(256, 1) attn_mma()
{
    extern __shared__ char smem[];
    __half* Qhi = (__half*)(smem + AT_QHI);
    __half* Qlo = (__half*)(smem + AT_QLO);
    __half* Khi = (__half*)(smem + AT_KHI);
    __half* Klo = (__half*)(smem + AT_KLO);
    __half* Vthi = (__half*)(smem + AT_VHI);
    __half* Vtlo = (__half*)(smem + AT_VLO);

    const int tid = threadIdx.x;
    const int wid = tid >> 5;
    const int lane = tid & 31;
    const int g = lane >> 2;         // fragment row group 0..7
    const int c = lane & 3;          // fragment col quad 0..3
    const int m0 = wid * 16;         // warp's q-row base within tile
    const int bh = blockIdx.y;
    const int q0 = blockIdx.x * 128;

    const float* qbase = g_q + (size_t)bh*S_*DH_;
    const float* kbase = g_k + (size_t)bh*S_*DH_;
    const float* vbase = g_v + (size_t)bh*S_*DH_;

    // gmem load mapping: idx = u*256 + tid -> r = idx>>4 (row), c4 = idx&15
    const int lr = tid >> 4;         // +16 per u
    const int lc4 = tid & 15;

    // ---- load Q tile once ----
    #pragma unroll
    for (int u = 0; u < 8; u++) {
        int r = lr + u*16;
        float4 qv = *(const float4*)&qbase[(size_t)(q0 + r)*DH_ + lc4*4];
        int off = r*TLD + lc4*4;
        __half h0,l0,h1,l1,h2,l2,h3,l3;
        cvt_hilo(qv.x, h0, l0); cvt_hilo(qv.y, h1, l1);
        cvt_hilo(qv.z, h2, l2); cvt_hilo(qv.w, h3, l3);
        ((__half2*)&Qhi[off])[0] = __halves2half2(h0, h1);
        ((__half2*)&Qhi[off])[1] = __halves2half2(h2, h3);
        ((__half2*)&Qlo[off])[0] = __halves2half2(l0, l1);
        ((__half2*)&Qlo[off])[1] = __halves2half2(l2, l3);
    }

    float O[8][4];                   // 8 n-tiles x m16n8 acc
    #pragma unroll
    for (int n = 0; n < 8; n++)
        #pragma unroll
        for (int t = 0; t < 4; t++) O[n][t] = 0.f;
    float mr0 = -INFINITY, mr1 = -INFINITY;   // rows g, g+8
    float lr0 = 0.f, lr1 = 0.f;

    for (int kt = 0; kt < S_/128; kt++) {
        const int k0g = kt * 128;
        // ---- prefetch K,V gmem -> regs (overlaps prior compute) ----
        float4 rk[8], rv[8];
        #pragma unroll
        for (int u = 0; u < 8; u++) {
            int r = lr + u*16;
            rk[u] = *(const float4*)&kbase[(size_t)(k0g + r)*DH_ + lc4*4];
            rv[u] = *(const float4*)&vbase[(size_t)(k0g + r)*DH_ + lc4*4];
        }
        __syncthreads();    // (a) all warps done reading prev K/V (Q ready @kt=0)
        #pragma unroll
        for (int u = 0; u < 8; u++) {
            int r = lr + u*16;
            int off = r*TLD + lc4*4;
            __half h0,l0,h1,l1,h2,l2,h3,l3;
            cvt_hilo(rk[u].x, h0, l0); cvt_hilo(rk[u].y, h1, l1);
            cvt_hilo(rk[u].z, h2, l2); cvt_hilo(rk[u].w, h3, l3);
            ((__half2*)&Khi[off])[0] = __halves2half2(h0, h1);
            ((__half2*)&Khi[off])[1] = __halves2half2(h2, h3);
            ((__half2*)&Klo[off])[0] = __halves2half2(l0, l1);
            ((__half2*)&Klo[off])[1] = __halves2half2(l2, l3);
            // V transposed: Vt[d][key]
            cvt_hilo(rv[u].x, h0, l0); cvt_hilo(rv[u].y, h1, l1);
            cvt_hilo(rv[u].z, h2, l2); cvt_hilo(rv[u].w, h3, l3);
            Vthi[(lc4*4+0)*VLD2 + r] = h0; Vtlo[(lc4*4+0)*VLD2 + r] = l0;
            Vthi[(lc4*4+1)*VLD2 + r] = h1; Vtlo[(lc4*4+1)*VLD2 + r] = l1;
            Vthi[(lc4*4+2)*VLD2 + r] = h2; Vtlo[(lc4*4+2)*VLD2 + r] = l2;
            Vthi[(lc4*4+3)*VLD2 + r] = h3; Vtlo[(lc4*4+3)*VLD2 + r] = l3;
        }
        __syncthreads();    // (b) K/V tile ready

        // ---- S = Q K^T (3-pass), register accumulators ----
        float sacc[16][4];
        #pragma unroll
        for (int n = 0; n < 16; n++)
            #pragma unroll
            for (int t = 0; t < 4; t++) sacc[n][t] = 0.f;

        #pragma unroll
        for (int kk = 0; kk < 64; kk += 16) {
            uint32_t qh[4], ql[4];
            qh[0] = *(const uint32_t*)&Qhi[(m0+g)*TLD   + kk + 2*c];
            qh[1] = *(const uint32_t*)&Qhi[(m0+g+8)*TLD + kk + 2*c];
            qh[2] = *(const uint32_t*)&Qhi[(m0+g)*TLD   + kk + 8 + 2*c];
            qh[3] = *(const uint32_t*)&Qhi[(m0+g+8)*TLD + kk + 8 + 2*c];
            ql[0] = *(const uint32_t*)&Qlo[(m0+g)*TLD   + kk + 2*c];
            ql[1] = *(const uint32_t*)&Qlo[(m0+g+8)*TLD + kk + 2*c];
            ql[2] = *(const uint32_t*)&Qlo[(m0+g)*TLD   + kk + 8 + 2*c];
            ql[3] = *(const uint32_t*)&Qlo[(m0+g+8)*TLD + kk + 8 + 2*c];
            #pragma unroll
            for (int n = 0; n < 16; n++) {
                uint32_t kh[2], kl[2];
                kh[0] = *(const uint32_t*)&Khi[(n*8+g)*TLD + kk + 2*c];
                kh[1] = *(const uint32_t*)&Khi[(n*8+g)*TLD + kk + 8 + 2*c];
                kl[0] = *(const uint32_t*)&Klo[(n*8+g)*TLD + kk + 2*c];
                kl[1] = *(const uint32_t*)&Klo[(n*8+g)*TLD + kk + 8 + 2*c];
                mma16816(sacc[n], qh, kh);
                mma16816(sacc[n], qh, kl);
                mma16816(sacc[n], ql, kh);
            }
        }

        // ---- register softmax (rows g, g+8; quad shfl reductions) ----
        float mx0 = -INFINITY, mx1 = -INFINITY;
        #pragma unroll
        for (int n = 0; n < 16; n++) {
            sacc[n][0] *= 0.125f; sacc[n][1] *= 0.125f;
            sacc[n][2] *= 0.125f; sacc[n][3] *= 0.125f;
            mx0 = fmaxf(mx0, fmaxf(sacc[n][0], sacc[n][1]));
            mx1 = fmaxf(mx1, fmaxf(sacc[n][2], sacc[n][3]));
        }
        mx0 = fmaxf(mx0, __shfl_xor_sync(0xffffffffu, mx0, 1));
        mx0 = fmaxf(mx0, __shfl_xor_sync(0xffffffffu, mx0, 2));
        mx1 = fmaxf(mx1, __shfl_xor_sync(0xffffffffu, mx1, 1));
        mx1 = fmaxf(mx1, __shfl_xor_sync(0xffffffffu, mx1, 2));
        float m0n = fmaxf(mr0, mx0), m1n = fmaxf(mr1, mx1);
        float al0 = __expf(mr0 - m0n), al1 = __expf(mr1 - m1n);
        mr0 = m0n; mr1 = m1n;

        uint32_t pa[8][4];
        float sum0 = 0.f, sum1 = 0.f;
        #pragma unroll
        for (int j = 0; j < 8; j++) {
            float p00 = __expf(sacc[2*j][0] - m0n);
            float p01 = __expf(sacc[2*j][1] - m0n);
            float p10 = __expf(sacc[2*j][2] - m1n);
            float p11 = __expf(sacc[2*j][3] - m1n);
            float p04 = __expf(sacc[2*j+1][0] - m0n);
            float p05 = __expf(sacc[2*j+1][1] - m0n);
            float p14 = __expf(sacc[2*j+1][2] - m1n);
            float p15 = __expf(sacc[2*j+1][3] - m1n);
            sum0 += p00 + p01 + p04 + p05;
            sum1 += p10 + p11 + p14 + p15;
            pa[j][0] = h2_to_u32(__floats2half2_rn(p00, p01));
            pa[j][1] = h2_to_u32(__floats2half2_rn(p10, p11));
            pa[j][2] = h2_to_u32(__floats2half2_rn(p04, p05));
            pa[j][3] = h2_to_u32(__floats2half2_rn(p14, p15));
        }
        sum0 += __shfl_xor_sync(0xffffffffu, sum0, 1);
        sum0 += __shfl_xor_sync(0xffffffffu, sum0, 2);
        sum1 += __shfl_xor_sync(0xffffffffu, sum1, 1);
        sum1 += __shfl_xor_sync(0xffffffffu, sum1, 2);
        lr0 = lr0*al0 + sum0;
        lr1 = lr1*al1 + sum1;

        // ---- O rescale + PV (V 2-pass) ----
        #pragma unroll
        for (int n = 0; n < 8; n++) {
            O[n][0] *= al0; O[n][1] *= al0;
            O[n][2] *= al1; O[n][3] *= al1;
        }
        #pragma unroll
        for (int j = 0; j < 8; j++) {
            #pragma unroll
            for (int nv = 0; nv < 8; nv++) {
                uint32_t bhh[2], bll[2];
                bhh[0] = *(const uint32_t*)&Vthi[(nv*8+g)*VLD2 + 16*j + 2*c];
                bhh[1] = *(const uint32_t*)&Vthi[(nv*8+g)*VLD2 + 16*j + 8 + 2*c];
                bll[0] = *(const uint32_t*)&Vtlo[(nv*8+g)*VLD2 + 16*j + 2*c];
                bll[1] = *(const uint32_t*)&Vtlo[(nv*8+g)*VLD2 + 16*j + 8 + 2*c];
                mma16816(O[nv], pa[j], bhh);
                mma16816(O[nv], pa[j], bll);
            }
        }
    }

    // ---- normalize + write [B,S,D] ----
    const int b = bh >> 4, h = bh & 15;
    float il0 = 1.0f / lr0, il1 = 1.0f / lr1;
    const int r0 = q0 + m0 + g, r1 = r0 + 8;
    #pragma unroll
    for (int nv = 0; nv < 8; nv++) {
        int col = h*DH_ + nv*8 + 2*c;
        float2 v0 = make_float2(O[nv][0]*il0, O[nv][1]*il0);
        float2 v1 = make_float2(O[nv][2]*il1, O[nv][3]*il1);
        *(float2*)&g_att[((size_t)(b*S_ + r0))*D_ + col] = v0;
        *(float2*)&g_att[((size_t)(b*S_ + r1))*D_ + col] = v1;
    }
}

// =====================================================================
// Launch
// =====================================================================
extern "C" void kernel_launch(void* const* d_in, const int* in_sizes, int n_in,
                              void* d_out, int out_size)
{
    const float* query  = (const float*)d_in[0];
    const float* keys   = (const float*)d_in[1];
    const float* values = (const float*)d_in[2];
    const float* Wq = (const float*)d_in[3];
    const float* bq = (const float*)d_in[4];
    const float* Wk = (const float*)d_in[5];
    const float* bk = (const float*)d_in[6];
    const float* Wv = (const float*)d_in[7];
    const float* bv = (const float*)d_in[8];
    const float* Wo = (const float*)d_in[9];
    const float* bo = (const float*)d_in[10];
    float* out = (float*)d_out;

    float *qp, *kp, *vp, *ap;
    cudaGetSymbolAddress((void**)&qp, g_q);
    cudaGetSymbolAddress((void**)&kp, g_k);
    cudaGetSymbolAddress((void**)&vp, g_v);
    cudaGetSymbolAddress((void**)&ap, g_att);

    cudaFuncSetAttribute(gemm_wmma<0>,
                         cudaFuncAttributeMaxDynamicSharedMemorySize, GW_SMEM);
    cudaFuncSetAttribute(gemm_wmma<1>,
                         cudaFuncAttributeMaxDynamicSharedMemorySize, GW_SMEM);
    cudaFuncSetAttribute(attn_mma,
                         cudaFuncAttributeMaxDynamicSharedMemorySize, ATT_SMEM);

    dim3 gemm_grid(D_/128, M_/128);   // (8, 32)
    gemm_wmma<1><<<gemm_grid, 256, GW_SMEM>>>(query,  Wq, bq, qp);
    gemm_wmma<1><<<gemm_grid, 256, GW_SMEM>>>(keys,   Wk, bk, kp);
    gemm_wmma<1><<<gemm_grid, 256, GW_SMEM>>>(values, Wv, bv, vp);

    attn_mma<<<dim3(S_/128, B_*H_), 256, ATT_SMEM>>>();

    gemm_wmma<0><<<gemm_grid, 256, GW_SMEM>>>(ap, Wo, bo, out);
}

// round 10
// speedup vs baseline: 3.0458x; 1.2165x over previous
#include <cuda_runtime.h>
#include <cuda_fp16.h>
#include <mma.h>
#include <math.h>
#include <stdint.h>

using namespace nvcuda;

// Problem constants
#define B_   2
#define S_   2048
#define D_   1024
#define H_   16
#define DH_  64
#define M_   (B_*S_)

// ---------------- scratch (device globals; no allocation) ----------------
__device__ float g_q[B_*H_*S_*DH_];     // [B,H,S,DH]
__device__ float g_k[B_*H_*S_*DH_];
__device__ float g_v[B_*H_*S_*DH_];
__device__ float g_att[B_*S_*D_];       // [B,S,D]

__device__ __forceinline__ void cvt_hilo(float x, __half& h, __half& l) {
    h = __float2half_rn(x);
    l = __float2half_rn(x - __half2float(h));
}

__device__ __forceinline__ uint32_t h2_to_u32(__half2 h) {
    union { __half2 h2; uint32_t u; } cv;
    cv.h2 = h;
    return cv.u;
}

// m16n8k16 fp16 MMA, fp32 accumulate (HMMA.16816)
__device__ __forceinline__ void mma16816(float* d, const uint32_t* a, const uint32_t* b) {
    asm volatile(
        "mma.sync.aligned.m16n8k16.row.col.f32.f16.f16.f32 "
        "{%0,%1,%2,%3}, {%4,%5,%6,%7}, {%8,%9}, {%0,%1,%2,%3};\n"
        : "+f"(d[0]), "+f"(d[1]), "+f"(d[2]), "+f"(d[3])
        : "r"(a[0]), "r"(a[1]), "r"(a[2]), "r"(a[3]), "r"(b[0]), "r"(b[1]));
}

// =====================================================================
// wmma fp16 split GEMM (3-pass hi/lo) — unchanged from R5/R7 (validated)
// =====================================================================
#define BKW 32
#define LDT 40
#define EPLD 36
#define GW_SMEM 73728

template<int MODE>
__global__ void __launch_bounds__(256) gemm_wmma(
    const float* __restrict__ A, const float* __restrict__ W,
    const float* __restrict__ bias, float* __restrict__ out)
{
    extern __shared__ char smem[];
    __half* sA_hi = (__half*)smem;
    __half* sA_lo = sA_hi + 128*LDT;
    __half* sW_hi = sA_lo + 128*LDT;
    __half* sW_lo = sW_hi + 128*LDT;
    float*  sEp   = (float*)smem;

    const int tid = threadIdx.x;
    const int wid = tid >> 5, lid = tid & 31;
    const int warp_m = wid & 1;
    const int warp_n = wid >> 1;
    const int m0 = blockIdx.y * 128, n0 = blockIdx.x * 128;

    const int lrow = tid >> 3;
    const int lc4  = tid & 7;

    wmma::fragment<wmma::accumulator, 16, 16, 16, float> acc[4][2];
    #pragma unroll
    for (int m = 0; m < 4; m++)
        #pragma unroll
        for (int n = 0; n < 2; n++) wmma::fill_fragment(acc[m][n], 0.0f);

    for (int kt = 0; kt < 1024/BKW; kt++) {
        const int k0 = kt * BKW;
        float4 ra[4], rw[4];
        #pragma unroll
        for (int u = 0; u < 4; u++) {
            int row = lrow + u*32;
            ra[u] = *(const float4*)&A[(size_t)(m0 + row)*1024 + k0 + lc4*4];
            rw[u] = *(const float4*)&W[(size_t)(n0 + row)*1024 + k0 + lc4*4];
        }
        __syncthreads();

        #pragma unroll
        for (int u = 0; u < 4; u++) {
            int row = lrow + u*32;
            int off = row*LDT + lc4*4;
            __half h0,l0,h1,l1,h2,l2,h3,l3;
            cvt_hilo(ra[u].x, h0, l0); cvt_hilo(ra[u].y, h1, l1);
            cvt_hilo(ra[u].z, h2, l2); cvt_hilo(ra[u].w, h3, l3);
            ((__half2*)&sA_hi[off])[0] = __halves2half2(h0, h1);
            ((__half2*)&sA_hi[off])[1] = __halves2half2(h2, h3);
            ((__half2*)&sA_lo[off])[0] = __halves2half2(l0, l1);
            ((__half2*)&sA_lo[off])[1] = __halves2half2(l2, l3);
            cvt_hilo(rw[u].x, h0, l0); cvt_hilo(rw[u].y, h1, l1);
            cvt_hilo(rw[u].z, h2, l2); cvt_hilo(rw[u].w, h3, l3);
            ((__half2*)&sW_hi[off])[0] = __halves2half2(h0, h1);
            ((__half2*)&sW_hi[off])[1] = __halves2half2(h2, h3);
            ((__half2*)&sW_lo[off])[0] = __halves2half2(l0, l1);
            ((__half2*)&sW_lo[off])[1] = __halves2half2(l2, l3);
        }
        __syncthreads();

        #pragma unroll
        for (int kk = 0; kk < BKW; kk += 16) {
            wmma::fragment<wmma::matrix_a, 16, 16, 16, __half, wmma::row_major> ahi[4], alo[4];
            #pragma unroll
            for (int m = 0; m < 4; m++) {
                int r = warp_m*64 + m*16;
                wmma::load_matrix_sync(ahi[m], &sA_hi[r*LDT + kk], LDT);
                wmma::load_matrix_sync(alo[m], &sA_lo[r*LDT + kk], LDT);
            }
            #pragma unroll
            for (int n = 0; n < 2; n++) {
                int c = warp_n*32 + n*16;
                wmma::fragment<wmma::matrix_b, 16, 16, 16, __half, wmma::col_major> bhi, blo;
                wmma::load_matrix_sync(bhi, &sW_hi[c*LDT + kk], LDT);
                wmma::load_matrix_sync(blo, &sW_lo[c*LDT + kk], LDT);
                #pragma unroll
                for (int m = 0; m < 4; m++) {
                    wmma::mma_sync(acc[m][n], ahi[m], bhi, acc[m][n]);
                    wmma::mma_sync(acc[m][n], ahi[m], blo, acc[m][n]);
                    wmma::mma_sync(acc[m][n], alo[m], bhi, acc[m][n]);
                }
            }
        }
    }

    __syncthreads();
    float* ep = sEp + wid * 64 * EPLD;
    #pragma unroll
    for (int m = 0; m < 4; m++)
        #pragma unroll
        for (int n = 0; n < 2; n++)
            wmma::store_matrix_sync(&ep[(m*16)*EPLD + n*16], acc[m][n],
                                    EPLD, wmma::mem_row_major);
    __syncwarp();

    const int nw0 = n0 + warp_n*32;
    #pragma unroll
    for (int rr = 0; rr < 2; rr++) {
        int r = lid + rr*32;
        int gm = m0 + warp_m*64 + r;
        if (MODE == 0) {
            #pragma unroll
            for (int c4 = 0; c4 < 8; c4++) {
                float4 v = *(float4*)&ep[r*EPLD + c4*4];
                int n = nw0 + c4*4;
                v.x += bias[n+0]; v.y += bias[n+1];
                v.z += bias[n+2]; v.w += bias[n+3];
                *(float4*)&out[(size_t)gm*1024 + n] = v;
            }
        } else {
            int b = gm >> 11, s = gm & 2047;
            int h = nw0 >> 6, d0 = nw0 & 63;
            size_t base = (((size_t)(b*H_ + h))*S_ + s)*DH_ + d0;
            #pragma unroll
            for (int c4 = 0; c4 < 8; c4++) {
                float4 v = *(float4*)&ep[r*EPLD + c4*4];
                int n = nw0 + c4*4;
                v.x += bias[n+0]; v.y += bias[n+1];
                v.z += bias[n+2]; v.w += bias[n+3];
                *(float4*)&out[base + c4*4] = v;
            }
        }
    }
}

// =====================================================================
// Flash attention on raw mma.sync m16n8k16 — register-resident S/P/O.
// One CTA = (b,h) x 128 q-rows, 8 warps x 16 rows.
// QK^T: 2-pass (Q hi/lo split, K single fp16).
// PV:   single-pass (P fp16, V fp16).
// Error budget calibrated on R7/R9 measurement (P-rounding => 7.1e-5);
// K/V rounding terms are same-order => predicted ~1.3e-4 total.
// smem: Q hi/lo [128][TLD], K hi [128][TLD], Vt hi [64][VLD2] = 71 KB.
// =====================================================================
#define TLD 72          // Q/K leading dim (halves): fragment LDS conflict-free
#define VLD2 136        // Vt leading dim (halves): conflict-free

#define AT_QHI 0
#define AT_QLO (AT_QHI + 128*TLD*2)      // 18432
#define AT_KHI (AT_QLO + 128*TLD*2)      // 36864
#define AT_VHI (AT_KHI + 128*TLD*2)      // 55296
#define ATT_SMEM (AT_VHI + 64*VLD2*2)    // 72704

__global__ void __launch_bounds__(256, 1) attn_mma()
{
    extern __shared__ char smem[];
    __half* Qhi = (__half*)(smem + AT_QHI);
    __half* Qlo = (__half*)(smem + AT_QLO);
    __half* Khi = (__half*)(smem + AT_KHI);
    __half* Vthi = (__half*)(smem + AT_VHI);

    const int tid = threadIdx.x;
    const int wid = tid >> 5;
    const int lane = tid & 31;
    const int g = lane >> 2;         // fragment row group 0..7
    const int c = lane & 3;          // fragment col quad 0..3
    const int m0 = wid * 16;         // warp's q-row base within tile
    const int bh = blockIdx.y;
    const int q0 = blockIdx.x * 128;

    const float* qbase = g_q + (size_t)bh*S_*DH_;
    const float* kbase = g_k + (size_t)bh*S_*DH_;
    const float* vbase = g_v + (size_t)bh*S_*DH_;

    // gmem load mapping: idx = u*256 + tid -> r = idx>>4 (row), c4 = idx&15
    const int lr = tid >> 4;         // +16 per u
    const int lc4 = tid & 15;

    // ---- load Q tile once (hi/lo split) ----
    #pragma unroll
    for (int u = 0; u < 8; u++) {
        int r = lr + u*16;
        float4 qv = *(const float4*)&qbase[(size_t)(q0 + r)*DH_ + lc4*4];
        int off = r*TLD + lc4*4;
        __half h0,l0,h1,l1,h2,l2,h3,l3;
        cvt_hilo(qv.x, h0, l0); cvt_hilo(qv.y, h1, l1);
        cvt_hilo(qv.z, h2, l2); cvt_hilo(qv.w, h3, l3);
        ((__half2*)&Qhi[off])[0] = __halves2half2(h0, h1);
        ((__half2*)&Qhi[off])[1] = __halves2half2(h2, h3);
        ((__half2*)&Qlo[off])[0] = __halves2half2(l0, l1);
        ((__half2*)&Qlo[off])[1] = __halves2half2(l2, l3);
    }

    float O[8][4];                   // 8 n-tiles x m16n8 acc
    #pragma unroll
    for (int n = 0; n < 8; n++)
        #pragma unroll
        for (int t = 0; t < 4; t++) O[n][t] = 0.f;
    float mr0 = -INFINITY, mr1 = -INFINITY;   // rows g, g+8
    float lr0 = 0.f, lr1 = 0.f;

    for (int kt = 0; kt < S_/128; kt++) {
        const int k0g = kt * 128;
        // ---- prefetch K,V gmem -> regs (overlaps prior compute) ----
        float4 rk[8], rv[8];
        #pragma unroll
        for (int u = 0; u < 8; u++) {
            int r = lr + u*16;
            rk[u] = *(const float4*)&kbase[(size_t)(k0g + r)*DH_ + lc4*4];
            rv[u] = *(const float4*)&vbase[(size_t)(k0g + r)*DH_ + lc4*4];
        }
        __syncthreads();    // (a) all warps done reading prev K/V (Q ready @kt=0)
        #pragma unroll
        for (int u = 0; u < 8; u++) {
            int r = lr + u*16;
            int off = r*TLD + lc4*4;
            __half h0 = __float2half_rn(rk[u].x), h1 = __float2half_rn(rk[u].y);
            __half h2 = __float2half_rn(rk[u].z), h3 = __float2half_rn(rk[u].w);
            ((__half2*)&Khi[off])[0] = __halves2half2(h0, h1);
            ((__half2*)&Khi[off])[1] = __halves2half2(h2, h3);
            // V transposed: Vt[d][key]
            h0 = __float2half_rn(rv[u].x); h1 = __float2half_rn(rv[u].y);
            h2 = __float2half_rn(rv[u].z); h3 = __float2half_rn(rv[u].w);
            Vthi[(lc4*4+0)*VLD2 + r] = h0;
            Vthi[(lc4*4+1)*VLD2 + r] = h1;
            Vthi[(lc4*4+2)*VLD2 + r] = h2;
            Vthi[(lc4*4+3)*VLD2 + r] = h3;
        }
        __syncthreads();    // (b) K/V tile ready

        // ---- S = Q K^T (2-pass: Q split, K single) ----
        float sacc[16][4];
        #pragma unroll
        for (int n = 0; n < 16; n++)
            #pragma unroll
            for (int t = 0; t < 4; t++) sacc[n][t] = 0.f;

        #pragma unroll
        for (int kk = 0; kk < 64; kk += 16) {
            uint32_t qh[4], ql[4];
            qh[0] = *(const uint32_t*)&Qhi[(m0+g)*TLD   + kk + 2*c];
            qh[1] = *(const uint32_t*)&Qhi[(m0+g+8)*TLD + kk + 2*c];
            qh[2] = *(const uint32_t*)&Qhi[(m0+g)*TLD   + kk + 8 + 2*c];
            qh[3] = *(const uint32_t*)&Qhi[(m0+g+8)*TLD + kk + 8 + 2*c];
            ql[0] = *(const uint32_t*)&Qlo[(m0+g)*TLD   + kk + 2*c];
            ql[1] = *(const uint32_t*)&Qlo[(m0+g+8)*TLD + kk + 2*c];
            ql[2] = *(const uint32_t*)&Qlo[(m0+g)*TLD   + kk + 8 + 2*c];
            ql[3] = *(const uint32_t*)&Qlo[(m0+g+8)*TLD + kk + 8 + 2*c];
            #pragma unroll
            for (int n = 0; n < 16; n++) {
                uint32_t kh[2];
                kh[0] = *(const uint32_t*)&Khi[(n*8+g)*TLD + kk + 2*c];
                kh[1] = *(const uint32_t*)&Khi[(n*8+g)*TLD + kk + 8 + 2*c];
                mma16816(sacc[n], qh, kh);
                mma16816(sacc[n], ql, kh);
            }
        }

        // ---- register softmax (rows g, g+8; quad shfl reductions) ----
        float mx0 = -INFINITY, mx1 = -INFINITY;
        #pragma unroll
        for (int n = 0; n < 16; n++) {
            sacc[n][0] *= 0.125f; sacc[n][1] *= 0.125f;
            sacc[n][2] *= 0.125f; sacc[n][3] *= 0.125f;
            mx0 = fmaxf(mx0, fmaxf(sacc[n][0], sacc[n][1]));
            mx1 = fmaxf(mx1, fmaxf(sacc[n][2], sacc[n][3]));
        }
        mx0 = fmaxf(mx0, __shfl_xor_sync(0xffffffffu, mx0, 1));
        mx0 = fmaxf(mx0, __shfl_xor_sync(0xffffffffu, mx0, 2));
        mx1 = fmaxf(mx1, __shfl_xor_sync(0xffffffffu, mx1, 1));
        mx1 = fmaxf(mx1, __shfl_xor_sync(0xffffffffu, mx1, 2));
        float m0n = fmaxf(mr0, mx0), m1n = fmaxf(mr1, mx1);
        float al0 = __expf(mr0 - m0n), al1 = __expf(mr1 - m1n);
        mr0 = m0n; mr1 = m1n;

        uint32_t pa[8][4];
        float sum0 = 0.f, sum1 = 0.f;
        #pragma unroll
        for (int j = 0; j < 8; j++) {
            float p00 = __expf(sacc[2*j][0] - m0n);
            float p01 = __expf(sacc[2*j][1] - m0n);
            float p10 = __expf(sacc[2*j][2] - m1n);
            float p11 = __expf(sacc[2*j][3] - m1n);
            float p04 = __expf(sacc[2*j+1][0] - m0n);
            float p05 = __expf(sacc[2*j+1][1] - m0n);
            float p14 = __expf(sacc[2*j+1][2] - m1n);
            float p15 = __expf(sacc[2*j+1][3] - m1n);
            sum0 += p00 + p01 + p04 + p05;
            sum1 += p10 + p11 + p14 + p15;
            pa[j][0] = h2_to_u32(__floats2half2_rn(p00, p01));
            pa[j][1] = h2_to_u32(__floats2half2_rn(p10, p11));
            pa[j][2] = h2_to_u32(__floats2half2_rn(p04, p05));
            pa[j][3] = h2_to_u32(__floats2half2_rn(p14, p15));
        }
        sum0 += __shfl_xor_sync(0xffffffffu, sum0, 1);
        sum0 += __shfl_xor_sync(0xffffffffu, sum0, 2);
        sum1 += __shfl_xor_sync(0xffffffffu, sum1, 1);
        sum1 += __shfl_xor_sync(0xffffffffu, sum1, 2);
        lr0 = lr0*al0 + sum0;
        lr1 = lr1*al1 + sum1;

        // ---- O rescale + PV (single pass) ----
        #pragma unroll
        for (int n = 0; n < 8; n++) {
            O[n][0] *= al0; O[n][1] *= al0;
            O[n][2] *= al1; O[n][3] *= al1;
        }
        #pragma unroll
        for (int j = 0; j < 8; j++) {
            #pragma unroll
            for (int nv = 0; nv < 8; nv++) {
                uint32_t bhh[2];
                bhh[0] = *(const uint32_t*)&Vthi[(nv*8+g)*VLD2 + 16*j + 2*c];
                bhh[1] = *(const uint32_t*)&Vthi[(nv*8+g)*VLD2 + 16*j + 8 + 2*c];
                mma16816(O[nv], pa[j], bhh);
            }
        }
    }

    // ---- normalize + write [B,S,D] ----
    const int b = bh >> 4, h = bh & 15;
    float il0 = 1.0f / lr0, il1 = 1.0f / lr1;
    const int r0 = q0 + m0 + g, r1 = r0 + 8;
    #pragma unroll
    for (int nv = 0; nv < 8; nv++) {
        int col = h*DH_ + nv*8 + 2*c;
        float2 v0 = make_float2(O[nv][0]*il0, O[nv][1]*il0);
        float2 v1 = make_float2(O[nv][2]*il1, O[nv][3]*il1);
        *(float2*)&g_att[((size_t)(b*S_ + r0))*D_ + col] = v0;
        *(float2*)&g_att[((size_t)(b*S_ + r1))*D_ + col] = v1;
    }
}

// =====================================================================
// Launch
// =====================================================================
extern "C" void kernel_launch(void* const* d_in, const int* in_sizes, int n_in,
                              void* d_out, int out_size)
{
    const float* query  = (const float*)d_in[0];
    const float* keys   = (const float*)d_in[1];
    const float* values = (const float*)d_in[2];
    const float* Wq = (const float*)d_in[3];
    const float* bq = (const float*)d_in[4];
    const float* Wk = (const float*)d_in[5];
    const float* bk = (const float*)d_in[6];
    const float* Wv = (const float*)d_in[7];
    const float* bv = (const float*)d_in[8];
    const float* Wo = (const float*)d_in[9];
    const float* bo = (const float*)d_in[10];
    float* out = (float*)d_out;

    float *qp, *kp, *vp, *ap;
    cudaGetSymbolAddress((void**)&qp, g_q);
    cudaGetSymbolAddress((void**)&kp, g_k);
    cudaGetSymbolAddress((void**)&vp, g_v);
    cudaGetSymbolAddress((void**)&ap, g_att);

    cudaFuncSetAttribute(gemm_wmma<0>,
                         cudaFuncAttributeMaxDynamicSharedMemorySize, GW_SMEM);
    cudaFuncSetAttribute(gemm_wmma<1>,
                         cudaFuncAttributeMaxDynamicSharedMemorySize, GW_SMEM);
    cudaFuncSetAttribute(attn_mma,
                         cudaFuncAttributeMaxDynamicSharedMemorySize, ATT_SMEM);

    dim3 gemm_grid(D_/128, M_/128);   // (8, 32)
    gemm_wmma<1><<<gemm_grid, 256, GW_SMEM>>>(query,  Wq, bq, qp);
    gemm_wmma<1><<<gemm_grid, 256, GW_SMEM>>>(keys,   Wk, bk, kp);
    gemm_wmma<1><<<gemm_grid, 256, GW_SMEM>>>(values, Wv, bv, vp);

    attn_mma<<<dim3(S_/128, B_*H_), 256, ATT_SMEM>>>();

    gemm_wmma<0><<<gemm_grid, 256, GW_SMEM>>>(ap, Wo, bo, out);
}

// round 11
// speedup vs baseline: 3.6057x; 1.1838x over previous
#include <cuda_runtime.h>
#include <cuda_fp16.h>
#include <mma.h>
#include <math.h>
#include <stdint.h>

using namespace nvcuda;

// Problem constants
#define B_   2
#define S_   2048
#define D_   1024
#define H_   16
#define DH_  64
#define M_   (B_*S_)

// ---------------- scratch (device globals; no allocation) ----------------
__device__ float g_q[B_*H_*S_*DH_];     // [B,H,S,DH]
__device__ float g_k[B_*H_*S_*DH_];
__device__ float g_v[B_*H_*S_*DH_];
__device__ float g_att[B_*S_*D_];       // [B,S,D]

__device__ __forceinline__ void cvt_hilo(float x, __half& h, __half& l) {
    h = __float2half_rn(x);
    l = __float2half_rn(x - __half2float(h));
}

__device__ __forceinline__ uint32_t h2_to_u32(__half2 h) {
    union { __half2 h2; uint32_t u; } cv;
    cv.h2 = h;
    return cv.u;
}

// m16n8k16 fp16 MMA, fp32 accumulate (HMMA.16816)
__device__ __forceinline__ void mma16816(float* d, const uint32_t* a, const uint32_t* b) {
    asm volatile(
        "mma.sync.aligned.m16n8k16.row.col.f32.f16.f16.f32 "
        "{%0,%1,%2,%3}, {%4,%5,%6,%7}, {%8,%9}, {%0,%1,%2,%3};\n"
        : "+f"(d[0]), "+f"(d[1]), "+f"(d[2]), "+f"(d[3])
        : "r"(a[0]), "r"(a[1]), "r"(a[2]), "r"(a[3]), "r"(b[0]), "r"(b[1]));
}

// =====================================================================
// wmma fp16 split GEMM — 2-pass: A exact (hi+lo), W single fp16.
// Error budget: W-rounding => ~2.8e-4 per GEMM rel err (calibrated model,
// runs conservative); acceptable vs 1e-3 gate with attention at 1.04e-4.
// C[m][n] = sum_k A[m][k]*W[n][k] + bias[n]; M=4096, N=1024, K=1024.
// CTA tile 128x128, BK=32, 256 threads = 8 warps (2m x 4n), warp 64x32.
// =====================================================================
#define BKW 32
#define LDT 40
#define EPLD 36
#define GW_SMEM 73728

template<int MODE>
__global__ void __launch_bounds__(256) gemm_wmma(
    const float* __restrict__ A, const float* __restrict__ W,
    const float* __restrict__ bias, float* __restrict__ out)
{
    extern __shared__ char smem[];
    __half* sA_hi = (__half*)smem;
    __half* sA_lo = sA_hi + 128*LDT;
    __half* sW_hi = sA_lo + 128*LDT;
    float*  sEp   = (float*)smem;

    const int tid = threadIdx.x;
    const int wid = tid >> 5, lid = tid & 31;
    const int warp_m = wid & 1;
    const int warp_n = wid >> 1;
    const int m0 = blockIdx.y * 128, n0 = blockIdx.x * 128;

    const int lrow = tid >> 3;
    const int lc4  = tid & 7;

    wmma::fragment<wmma::accumulator, 16, 16, 16, float> acc[4][2];
    #pragma unroll
    for (int m = 0; m < 4; m++)
        #pragma unroll
        for (int n = 0; n < 2; n++) wmma::fill_fragment(acc[m][n], 0.0f);

    for (int kt = 0; kt < 1024/BKW; kt++) {
        const int k0 = kt * BKW;
        float4 ra[4], rw[4];
        #pragma unroll
        for (int u = 0; u < 4; u++) {
            int row = lrow + u*32;
            ra[u] = *(const float4*)&A[(size_t)(m0 + row)*1024 + k0 + lc4*4];
            rw[u] = *(const float4*)&W[(size_t)(n0 + row)*1024 + k0 + lc4*4];
        }
        __syncthreads();

        #pragma unroll
        for (int u = 0; u < 4; u++) {
            int row = lrow + u*32;
            int off = row*LDT + lc4*4;
            __half h0,l0,h1,l1,h2,l2,h3,l3;
            cvt_hilo(ra[u].x, h0, l0); cvt_hilo(ra[u].y, h1, l1);
            cvt_hilo(ra[u].z, h2, l2); cvt_hilo(ra[u].w, h3, l3);
            ((__half2*)&sA_hi[off])[0] = __halves2half2(h0, h1);
            ((__half2*)&sA_hi[off])[1] = __halves2half2(h2, h3);
            ((__half2*)&sA_lo[off])[0] = __halves2half2(l0, l1);
            ((__half2*)&sA_lo[off])[1] = __halves2half2(l2, l3);
            h0 = __float2half_rn(rw[u].x); h1 = __float2half_rn(rw[u].y);
            h2 = __float2half_rn(rw[u].z); h3 = __float2half_rn(rw[u].w);
            ((__half2*)&sW_hi[off])[0] = __halves2half2(h0, h1);
            ((__half2*)&sW_hi[off])[1] = __halves2half2(h2, h3);
        }
        __syncthreads();

        #pragma unroll
        for (int kk = 0; kk < BKW; kk += 16) {
            wmma::fragment<wmma::matrix_a, 16, 16, 16, __half, wmma::row_major> ahi[4], alo[4];
            #pragma unroll
            for (int m = 0; m < 4; m++) {
                int r = warp_m*64 + m*16;
                wmma::load_matrix_sync(ahi[m], &sA_hi[r*LDT + kk], LDT);
                wmma::load_matrix_sync(alo[m], &sA_lo[r*LDT + kk], LDT);
            }
            #pragma unroll
            for (int n = 0; n < 2; n++) {
                int c = warp_n*32 + n*16;
                wmma::fragment<wmma::matrix_b, 16, 16, 16, __half, wmma::col_major> bhi;
                wmma::load_matrix_sync(bhi, &sW_hi[c*LDT + kk], LDT);
                #pragma unroll
                for (int m = 0; m < 4; m++) {
                    wmma::mma_sync(acc[m][n], ahi[m], bhi, acc[m][n]);
                    wmma::mma_sync(acc[m][n], alo[m], bhi, acc[m][n]);
                }
            }
        }
    }

    __syncthreads();
    float* ep = sEp + wid * 64 * EPLD;
    #pragma unroll
    for (int m = 0; m < 4; m++)
        #pragma unroll
        for (int n = 0; n < 2; n++)
            wmma::store_matrix_sync(&ep[(m*16)*EPLD + n*16], acc[m][n],
                                    EPLD, wmma::mem_row_major);
    __syncwarp();

    const int nw0 = n0 + warp_n*32;
    #pragma unroll
    for (int rr = 0; rr < 2; rr++) {
        int r = lid + rr*32;
        int gm = m0 + warp_m*64 + r;
        if (MODE == 0) {
            #pragma unroll
            for (int c4 = 0; c4 < 8; c4++) {
                float4 v = *(float4*)&ep[r*EPLD + c4*4];
                int n = nw0 + c4*4;
                v.x += bias[n+0]; v.y += bias[n+1];
                v.z += bias[n+2]; v.w += bias[n+3];
                *(float4*)&out[(size_t)gm*1024 + n] = v;
            }
        } else {
            int b = gm >> 11, s = gm & 2047;
            int h = nw0 >> 6, d0 = nw0 & 63;
            size_t base = (((size_t)(b*H_ + h))*S_ + s)*DH_ + d0;
            #pragma unroll
            for (int c4 = 0; c4 < 8; c4++) {
                float4 v = *(float4*)&ep[r*EPLD + c4*4];
                int n = nw0 + c4*4;
                v.x += bias[n+0]; v.y += bias[n+1];
                v.z += bias[n+2]; v.w += bias[n+3];
                *(float4*)&out[base + c4*4] = v;
            }
        }
    }
}

// =====================================================================
// Flash attention on raw mma.sync m16n8k16 — register-resident S/P/O.
// Unchanged from R10 (307.5us, validated).
// QK^T: 2-pass (Q hi/lo, K single). PV: single-pass.
// =====================================================================
#define TLD 72          // Q/K leading dim (halves): fragment LDS conflict-free
#define VLD2 136        // Vt leading dim (halves): conflict-free

#define AT_QHI 0
#define AT_QLO (AT_QHI + 128*TLD*2)      // 18432
#define AT_KHI (AT_QLO + 128*TLD*2)      // 36864
#define AT_VHI (AT_KHI + 128*TLD*2)      // 55296
#define ATT_SMEM (AT_VHI + 64*VLD2*2)    // 72704

__global__ void __launch_bounds__(256, 1) attn_mma()
{
    extern __shared__ char smem[];
    __half* Qhi = (__half*)(smem + AT_QHI);
    __half* Qlo = (__half*)(smem + AT_QLO);
    __half* Khi = (__half*)(smem + AT_KHI);
    __half* Vthi = (__half*)(smem + AT_VHI);

    const int tid = threadIdx.x;
    const int wid = tid >> 5;
    const int lane = tid & 31;
    const int g = lane >> 2;         // fragment row group 0..7
    const int c = lane & 3;          // fragment col quad 0..3
    const int m0 = wid * 16;         // warp's q-row base within tile
    const int bh = blockIdx.y;
    const int q0 = blockIdx.x * 128;

    const float* qbase = g_q + (size_t)bh*S_*DH_;
    const float* kbase = g_k + (size_t)bh*S_*DH_;
    const float* vbase = g_v + (size_t)bh*S_*DH_;

    // gmem load mapping: idx = u*256 + tid -> r = idx>>4 (row), c4 = idx&15
    const int lr = tid >> 4;         // +16 per u
    const int lc4 = tid & 15;

    // ---- load Q tile once (hi/lo split) ----
    #pragma unroll
    for (int u = 0; u < 8; u++) {
        int r = lr + u*16;
        float4 qv = *(const float4*)&qbase[(size_t)(q0 + r)*DH_ + lc4*4];
        int off = r*TLD + lc4*4;
        __half h0,l0,h1,l1,h2,l2,h3,l3;
        cvt_hilo(qv.x, h0, l0); cvt_hilo(qv.y, h1, l1);
        cvt_hilo(qv.z, h2, l2); cvt_hilo(qv.w, h3, l3);
        ((__half2*)&Qhi[off])[0] = __halves2half2(h0, h1);
        ((__half2*)&Qhi[off])[1] = __halves2half2(h2, h3);
        ((__half2*)&Qlo[off])[0] = __halves2half2(l0, l1);
        ((__half2*)&Qlo[off])[1] = __halves2half2(l2, l3);
    }

    float O[8][4];                   // 8 n-tiles x m16n8 acc
    #pragma unroll
    for (int n = 0; n < 8; n++)
        #pragma unroll
        for (int t = 0; t < 4; t++) O[n][t] = 0.f;
    float mr0 = -INFINITY, mr1 = -INFINITY;   // rows g, g+8
    float lr0 = 0.f, lr1 = 0.f;

    for (int kt = 0; kt < S_/128; kt++) {
        const int k0g = kt * 128;
        // ---- prefetch K,V gmem -> regs (overlaps prior compute) ----
        float4 rk[8], rv[8];
        #pragma unroll
        for (int u = 0; u < 8; u++) {
            int r = lr + u*16;
            rk[u] = *(const float4*)&kbase[(size_t)(k0g + r)*DH_ + lc4*4];
            rv[u] = *(const float4*)&vbase[(size_t)(k0g + r)*DH_ + lc4*4];
        }
        __syncthreads();    // (a) all warps done reading prev K/V (Q ready @kt=0)
        #pragma unroll
        for (int u = 0; u < 8; u++) {
            int r = lr + u*16;
            int off = r*TLD + lc4*4;
            __half h0 = __float2half_rn(rk[u].x), h1 = __float2half_rn(rk[u].y);
            __half h2 = __float2half_rn(rk[u].z), h3 = __float2half_rn(rk[u].w);
            ((__half2*)&Khi[off])[0] = __halves2half2(h0, h1);
            ((__half2*)&Khi[off])[1] = __halves2half2(h2, h3);
            // V transposed: Vt[d][key]
            h0 = __float2half_rn(rv[u].x); h1 = __float2half_rn(rv[u].y);
            h2 = __float2half_rn(rv[u].z); h3 = __float2half_rn(rv[u].w);
            Vthi[(lc4*4+0)*VLD2 + r] = h0;
            Vthi[(lc4*4+1)*VLD2 + r] = h1;
            Vthi[(lc4*4+2)*VLD2 + r] = h2;
            Vthi[(lc4*4+3)*VLD2 + r] = h3;
        }
        __syncthreads();    // (b) K/V tile ready

        // ---- S = Q K^T (2-pass: Q split, K single) ----
        float sacc[16][4];
        #pragma unroll
        for (int n = 0; n < 16; n++)
            #pragma unroll
            for (int t = 0; t < 4; t++) sacc[n][t] = 0.f;

        #pragma unroll
        for (int kk = 0; kk < 64; kk += 16) {
            uint32_t qh[4], ql[4];
            qh[0] = *(const uint32_t*)&Qhi[(m0+g)*TLD   + kk + 2*c];
            qh[1] = *(const uint32_t*)&Qhi[(m0+g+8)*TLD + kk + 2*c];
            qh[2] = *(const uint32_t*)&Qhi[(m0+g)*TLD   + kk + 8 + 2*c];
            qh[3] = *(const uint32_t*)&Qhi[(m0+g+8)*TLD + kk + 8 + 2*c];
            ql[0] = *(const uint32_t*)&Qlo[(m0+g)*TLD   + kk + 2*c];
            ql[1] = *(const uint32_t*)&Qlo[(m0+g+8)*TLD + kk + 2*c];
            ql[2] = *(const uint32_t*)&Qlo[(m0+g)*TLD   + kk + 8 + 2*c];
            ql[3] = *(const uint32_t*)&Qlo[(m0+g+8)*TLD + kk + 8 + 2*c];
            #pragma unroll
            for (int n = 0; n < 16; n++) {
                uint32_t kh[2];
                kh[0] = *(const uint32_t*)&Khi[(n*8+g)*TLD + kk + 2*c];
                kh[1] = *(const uint32_t*)&Khi[(n*8+g)*TLD + kk + 8 + 2*c];
                mma16816(sacc[n], qh, kh);
                mma16816(sacc[n], ql, kh);
            }
        }

        // ---- register softmax (rows g, g+8; quad shfl reductions) ----
        float mx0 = -INFINITY, mx1 = -INFINITY;
        #pragma unroll
        for (int n = 0; n < 16; n++) {
            sacc[n][0] *= 0.125f; sacc[n][1] *= 0.125f;
            sacc[n][2] *= 0.125f; sacc[n][3] *= 0.125f;
            mx0 = fmaxf(mx0, fmaxf(sacc[n][0], sacc[n][1]));
            mx1 = fmaxf(mx1, fmaxf(sacc[n][2], sacc[n][3]));
        }
        mx0 = fmaxf(mx0, __shfl_xor_sync(0xffffffffu, mx0, 1));
        mx0 = fmaxf(mx0, __shfl_xor_sync(0xffffffffu, mx0, 2));
        mx1 = fmaxf(mx1, __shfl_xor_sync(0xffffffffu, mx1, 1));
        mx1 = fmaxf(mx1, __shfl_xor_sync(0xffffffffu, mx1, 2));
        float m0n = fmaxf(mr0, mx0), m1n = fmaxf(mr1, mx1);
        float al0 = __expf(mr0 - m0n), al1 = __expf(mr1 - m1n);
        mr0 = m0n; mr1 = m1n;

        uint32_t pa[8][4];
        float sum0 = 0.f, sum1 = 0.f;
        #pragma unroll
        for (int j = 0; j < 8; j++) {
            float p00 = __expf(sacc[2*j][0] - m0n);
            float p01 = __expf(sacc[2*j][1] - m0n);
            float p10 = __expf(sacc[2*j][2] - m1n);
            float p11 = __expf(sacc[2*j][3] - m1n);
            float p04 = __expf(sacc[2*j+1][0] - m0n);
            float p05 = __expf(sacc[2*j+1][1] - m0n);
            float p14 = __expf(sacc[2*j+1][2] - m1n);
            float p15 = __expf(sacc[2*j+1][3] - m1n);
            sum0 += p00 + p01 + p04 + p05;
            sum1 += p10 + p11 + p14 + p15;
            pa[j][0] = h2_to_u32(__floats2half2_rn(p00, p01));
            pa[j][1] = h2_to_u32(__floats2half2_rn(p10, p11));
            pa[j][2] = h2_to_u32(__floats2half2_rn(p04, p05));
            pa[j][3] = h2_to_u32(__floats2half2_rn(p14, p15));
        }
        sum0 += __shfl_xor_sync(0xffffffffu, sum0, 1);
        sum0 += __shfl_xor_sync(0xffffffffu, sum0, 2);
        sum1 += __shfl_xor_sync(0xffffffffu, sum1, 1);
        sum1 += __shfl_xor_sync(0xffffffffu, sum1, 2);
        lr0 = lr0*al0 + sum0;
        lr1 = lr1*al1 + sum1;

        // ---- O rescale + PV (single pass) ----
        #pragma unroll
        for (int n = 0; n < 8; n++) {
            O[n][0] *= al0; O[n][1] *= al0;
            O[n][2] *= al1; O[n][3] *= al1;
        }
        #pragma unroll
        for (int j = 0; j < 8; j++) {
            #pragma unroll
            for (int nv = 0; nv < 8; nv++) {
                uint32_t bhh[2];
                bhh[0] = *(const uint32_t*)&Vthi[(nv*8+g)*VLD2 + 16*j + 2*c];
                bhh[1] = *(const uint32_t*)&Vthi[(nv*8+g)*VLD2 + 16*j + 8 + 2*c];
                mma16816(O[nv], pa[j], bhh);
            }
        }
    }

    // ---- normalize + write [B,S,D] ----
    const int b = bh >> 4, h = bh & 15;
    float il0 = 1.0f / lr0, il1 = 1.0f / lr1;
    const int r0 = q0 + m0 + g, r1 = r0 + 8;
    #pragma unroll
    for (int nv = 0; nv < 8; nv++) {
        int col = h*DH_ + nv*8 + 2*c;
        float2 v0 = make_float2(O[nv][0]*il0, O[nv][1]*il0);
        float2 v1 = make_float2(O[nv][2]*il1, O[nv][3]*il1);
        *(float2*)&g_att[((size_t)(b*S_ + r0))*D_ + col] = v0;
        *(float2*)&g_att[((size_t)(b*S_ + r1))*D_ + col] = v1;
    }
}

// =====================================================================
// Launch
// =====================================================================
extern "C" void kernel_launch(void* const* d_in, const int* in_sizes, int n_in,
                              void* d_out, int out_size)
{
    const float* query  = (const float*)d_in[0];
    const float* keys   = (const float*)d_in[1];
    const float* values = (const float*)d_in[2];
    const float* Wq = (const float*)d_in[3];
    const float* bq = (const float*)d_in[4];
    const float* Wk = (const float*)d_in[5];
    const float* bk = (const float*)d_in[6];
    const float* Wv = (const float*)d_in[7];
    const float* bv = (const float*)d_in[8];
    const float* Wo = (const float*)d_in[9];
    const float* bo = (const float*)d_in[10];
    float* out = (float*)d_out;

    float *qp, *kp, *vp, *ap;
    cudaGetSymbolAddress((void**)&qp, g_q);
    cudaGetSymbolAddress((void**)&kp, g_k);
    cudaGetSymbolAddress((void**)&vp, g_v);
    cudaGetSymbolAddress((void**)&ap, g_att);

    cudaFuncSetAttribute(gemm_wmma<0>,
                         cudaFuncAttributeMaxDynamicSharedMemorySize, GW_SMEM);
    cudaFuncSetAttribute(gemm_wmma<1>,
                         cudaFuncAttributeMaxDynamicSharedMemorySize, GW_SMEM);
    cudaFuncSetAttribute(attn_mma,
                         cudaFuncAttributeMaxDynamicSharedMemorySize, ATT_SMEM);

    dim3 gemm_grid(D_/128, M_/128);   // (8, 32)
    gemm_wmma<1><<<gemm_grid, 256, GW_SMEM>>>(query,  Wq, bq, qp);
    gemm_wmma<1><<<gemm_grid, 256, GW_SMEM>>>(keys,   Wk, bk, kp);
    gemm_wmma<1><<<gemm_grid, 256, GW_SMEM>>>(values, Wv, bv, vp);

    attn_mma<<<dim3(S_/128, B_*H_), 256, ATT_SMEM>>>();

    gemm_wmma<0><<<gemm_grid, 256, GW_SMEM>>>(ap, Wo, bo, out);
}

// round 12
// speedup vs baseline: 4.2911x; 1.1901x over previous
#include <cuda_runtime.h>
#include <cuda_fp16.h>
#include <mma.h>
#include <math.h>
#include <stdint.h>

using namespace nvcuda;

// Problem constants
#define B_   2
#define S_   2048
#define D_   1024
#define H_   16
#define DH_  64
#define M_   (B_*S_)

// ---------------- scratch (device globals; no allocation) ----------------
__device__ __half g_qh[B_*H_*S_*DH_];   // Q hi (pre-scaled by 0.125)
__device__ __half g_ql[B_*H_*S_*DH_];   // Q lo (pre-scaled)
__device__ __half g_kh[B_*H_*S_*DH_];   // K fp16
__device__ __half g_vh[B_*H_*S_*DH_];   // V fp16
__device__ float  g_att[B_*S_*D_];      // attention out [B,S,D] fp32

__device__ __forceinline__ void cvt_hilo(float x, __half& h, __half& l) {
    h = __float2half_rn(x);
    l = __float2half_rn(x - __half2float(h));
}

__device__ __forceinline__ uint32_t h2_to_u32(__half2 h) {
    union { __half2 h2; uint32_t u; } cv;
    cv.h2 = h;
    return cv.u;
}

// m16n8k16 fp16 MMA, fp32 accumulate (HMMA.16816)
__device__ __forceinline__ void mma16816(float* d, const uint32_t* a, const uint32_t* b) {
    asm volatile(
        "mma.sync.aligned.m16n8k16.row.col.f32.f16.f16.f32 "
        "{%0,%1,%2,%3}, {%4,%5,%6,%7}, {%8,%9}, {%0,%1,%2,%3};\n"
        : "+f"(d[0]), "+f"(d[1]), "+f"(d[2]), "+f"(d[3])
        : "r"(a[0]), "r"(a[1]), "r"(a[2]), "r"(a[3]), "r"(b[0]), "r"(b[1]));
}

__device__ __forceinline__ void ldsm_x4(uint32_t* r, uint32_t a) {
    asm volatile("ldmatrix.sync.aligned.m8n8.x4.shared.b16 {%0,%1,%2,%3}, [%4];"
        : "=r"(r[0]), "=r"(r[1]), "=r"(r[2]), "=r"(r[3]) : "r"(a));
}
__device__ __forceinline__ void ldsm_x4_t(uint32_t* r, uint32_t a) {
    asm volatile("ldmatrix.sync.aligned.m8n8.x4.trans.shared.b16 {%0,%1,%2,%3}, [%4];"
        : "=r"(r[0]), "=r"(r[1]), "=r"(r[2]), "=r"(r[3]) : "r"(a));
}

// =====================================================================
// wmma fp16 split GEMM — 2-pass: A exact (hi+lo), W single fp16.
// MODE 0: fp32 out [M][N] (final projection)
// MODE 1: Q -> hi/lo half pair [B,H,S,DH], scaled by 0.125
// MODE 2: K/V -> single half [B,H,S,DH]
// =====================================================================
#define BKW 32
#define LDT 40
#define EPLD 36
#define GW_SMEM 73728

template<int MODE>
__global__ void __launch_bounds__(256) gemm_wmma(
    const float* __restrict__ A, const float* __restrict__ W,
    const float* __restrict__ bias, float* __restrict__ outf,
    __half* __restrict__ outh_hi, __half* __restrict__ outh_lo)
{
    extern __shared__ char smem[];
    __half* sA_hi = (__half*)smem;
    __half* sA_lo = sA_hi + 128*LDT;
    __half* sW_hi = sA_lo + 128*LDT;
    float*  sEp   = (float*)smem;

    const int tid = threadIdx.x;
    const int wid = tid >> 5, lid = tid & 31;
    const int warp_m = wid & 1;
    const int warp_n = wid >> 1;
    const int m0 = blockIdx.y * 128, n0 = blockIdx.x * 128;

    const int lrow = tid >> 3;
    const int lc4  = tid & 7;

    wmma::fragment<wmma::accumulator, 16, 16, 16, float> acc[4][2];
    #pragma unroll
    for (int m = 0; m < 4; m++)
        #pragma unroll
        for (int n = 0; n < 2; n++) wmma::fill_fragment(acc[m][n], 0.0f);

    for (int kt = 0; kt < 1024/BKW; kt++) {
        const int k0 = kt * BKW;
        float4 ra[4], rw[4];
        #pragma unroll
        for (int u = 0; u < 4; u++) {
            int row = lrow + u*32;
            ra[u] = *(const float4*)&A[(size_t)(m0 + row)*1024 + k0 + lc4*4];
            rw[u] = *(const float4*)&W[(size_t)(n0 + row)*1024 + k0 + lc4*4];
        }
        __syncthreads();

        #pragma unroll
        for (int u = 0; u < 4; u++) {
            int row = lrow + u*32;
            int off = row*LDT + lc4*4;
            __half h0,l0,h1,l1,h2,l2,h3,l3;
            cvt_hilo(ra[u].x, h0, l0); cvt_hilo(ra[u].y, h1, l1);
            cvt_hilo(ra[u].z, h2, l2); cvt_hilo(ra[u].w, h3, l3);
            ((__half2*)&sA_hi[off])[0] = __halves2half2(h0, h1);
            ((__half2*)&sA_hi[off])[1] = __halves2half2(h2, h3);
            ((__half2*)&sA_lo[off])[0] = __halves2half2(l0, l1);
            ((__half2*)&sA_lo[off])[1] = __halves2half2(l2, l3);
            h0 = __float2half_rn(rw[u].x); h1 = __float2half_rn(rw[u].y);
            h2 = __float2half_rn(rw[u].z); h3 = __float2half_rn(rw[u].w);
            ((__half2*)&sW_hi[off])[0] = __halves2half2(h0, h1);
            ((__half2*)&sW_hi[off])[1] = __halves2half2(h2, h3);
        }
        __syncthreads();

        #pragma unroll
        for (int kk = 0; kk < BKW; kk += 16) {
            wmma::fragment<wmma::matrix_a, 16, 16, 16, __half, wmma::row_major> ahi[4], alo[4];
            #pragma unroll
            for (int m = 0; m < 4; m++) {
                int r = warp_m*64 + m*16;
                wmma::load_matrix_sync(ahi[m], &sA_hi[r*LDT + kk], LDT);
                wmma::load_matrix_sync(alo[m], &sA_lo[r*LDT + kk], LDT);
            }
            #pragma unroll
            for (int n = 0; n < 2; n++) {
                int c = warp_n*32 + n*16;
                wmma::fragment<wmma::matrix_b, 16, 16, 16, __half, wmma::col_major> bhi;
                wmma::load_matrix_sync(bhi, &sW_hi[c*LDT + kk], LDT);
                #pragma unroll
                for (int m = 0; m < 4; m++) {
                    wmma::mma_sync(acc[m][n], ahi[m], bhi, acc[m][n]);
                    wmma::mma_sync(acc[m][n], alo[m], bhi, acc[m][n]);
                }
            }
        }
    }

    __syncthreads();
    float* ep = sEp + wid * 64 * EPLD;
    #pragma unroll
    for (int m = 0; m < 4; m++)
        #pragma unroll
        for (int n = 0; n < 2; n++)
            wmma::store_matrix_sync(&ep[(m*16)*EPLD + n*16], acc[m][n],
                                    EPLD, wmma::mem_row_major);
    __syncwarp();

    const int nw0 = n0 + warp_n*32;
    #pragma unroll
    for (int rr = 0; rr < 2; rr++) {
        int r = lid + rr*32;
        int gm = m0 + warp_m*64 + r;
        if (MODE == 0) {
            #pragma unroll
            for (int c4 = 0; c4 < 8; c4++) {
                float4 v = *(float4*)&ep[r*EPLD + c4*4];
                int n = nw0 + c4*4;
                v.x += bias[n+0]; v.y += bias[n+1];
                v.z += bias[n+2]; v.w += bias[n+3];
                *(float4*)&outf[(size_t)gm*1024 + n] = v;
            }
        } else {
            int b = gm >> 11, s = gm & 2047;
            int h = nw0 >> 6, d0 = nw0 & 63;
            size_t base = (((size_t)(b*H_ + h))*S_ + s)*DH_ + d0;
            #pragma unroll
            for (int c4 = 0; c4 < 8; c4++) {
                float4 v = *(float4*)&ep[r*EPLD + c4*4];
                int n = nw0 + c4*4;
                v.x += bias[n+0]; v.y += bias[n+1];
                v.z += bias[n+2]; v.w += bias[n+3];
                if (MODE == 1) {
                    // scale by 1/sqrt(DH) here (power of 2: exact w.r.t. split)
                    v.x *= 0.125f; v.y *= 0.125f; v.z *= 0.125f; v.w *= 0.125f;
                    __half h0,l0,h1,l1,h2,l2,h3,l3;
                    cvt_hilo(v.x, h0, l0); cvt_hilo(v.y, h1, l1);
                    cvt_hilo(v.z, h2, l2); cvt_hilo(v.w, h3, l3);
                    uint2 hi = make_uint2(h2_to_u32(__halves2half2(h0, h1)),
                                          h2_to_u32(__halves2half2(h2, h3)));
                    uint2 lo = make_uint2(h2_to_u32(__halves2half2(l0, l1)),
                                          h2_to_u32(__halves2half2(l2, l3)));
                    *(uint2*)&outh_hi[base + c4*4] = hi;
                    *(uint2*)&outh_lo[base + c4*4] = lo;
                } else {
                    uint2 hv = make_uint2(
                        h2_to_u32(__floats2half2_rn(v.x, v.y)),
                        h2_to_u32(__floats2half2_rn(v.z, v.w)));
                    *(uint2*)&outh_hi[base + c4*4] = hv;
                }
            }
        }
    }
}

// =====================================================================
// Flash attention — raw mma.sync + ldmatrix, fp16 scratch inputs.
// One CTA = (b,h) x 128 q-rows, 8 warps x 16 rows.
// QK^T: 2-pass (Q hi/lo pre-split+pre-scaled by projection), K fp16.
// PV:   single-pass; V stored [key][d] row-major, loaded ldmatrix.trans.
// No cvt in the mainloop; fragment loads = ldmatrix.x4 (conflict-free,
// row stride 144B). 2 __syncthreads per key tile.
// =====================================================================
#define TLD 72          // leading dim (halves); 144B rows

#define AT_QHI 0
#define AT_QLO (AT_QHI + 128*TLD*2)      // 18432
#define AT_K   (AT_QLO + 128*TLD*2)      // 36864
#define AT_V   (AT_K   + 128*TLD*2)      // 55296
#define ATT_SMEM (AT_V + 128*TLD*2)      // 73728

__global__ void __launch_bounds__(256, 1) attn_mma()
{
    extern __shared__ char smem[];
    __half* Qhi = (__half*)(smem + AT_QHI);
    __half* Qlo = (__half*)(smem + AT_QLO);
    __half* Ks  = (__half*)(smem + AT_K);
    __half* Vs  = (__half*)(smem + AT_V);

    const int tid = threadIdx.x;
    const int wid = tid >> 5;
    const int lane = tid & 31;
    const int m0 = wid * 16;         // warp's q-row base within tile
    const int bh = blockIdx.y;
    const int q0 = blockIdx.x * 128;

    const __half* qh_base = g_qh + (size_t)bh*S_*DH_;
    const __half* ql_base = g_ql + (size_t)bh*S_*DH_;
    const __half* k_base  = g_kh + (size_t)bh*S_*DH_;
    const __half* v_base  = g_vh + (size_t)bh*S_*DH_;

    // gmem<->smem mapping: idx = u*256 + tid; row = idx>>3, cu = idx&7 (8x16B/row)
    const int lrow = tid >> 3;       // +32 per u
    const int lcu  = tid & 7;

    const uint32_t sb = (uint32_t)__cvta_generic_to_shared(smem);
    // ldmatrix per-lane base addresses
    const int li = lane >> 3;        // matrix index 0..3
    const int l7 = lane & 7;
    // Q A-frag: matrix i: row = m0 + (i&1)*8 + l7, col = (i>>1)*8 (+kk)
    const uint32_t aQ_off = ((uint32_t)((m0 + ((li & 1) << 3) + l7) * TLD
                                         + ((li >> 1) << 3)) << 1);
    const uint32_t aQhi = sb + AT_QHI + aQ_off;
    const uint32_t aQlo = sb + AT_QLO + aQ_off;
    // K B-frag: matrix i: key = (i>>1)*8 + l7 (+np*16), col = (i&1)*8 (+kk)
    const uint32_t aK = sb + AT_K +
        ((uint32_t)((((li >> 1) << 3) + l7) * TLD + ((li & 1) << 3)) << 1);
    // V B-frag (trans): matrix i: key = (i&1)*8 + l7 (+j*16), ncol = (i>>1)*8 (+nvp*16)
    const uint32_t aV = sb + AT_V +
        ((uint32_t)((((li & 1) << 3) + l7) * TLD + ((li >> 1) << 3)) << 1);

    // ---- load Q tile once (hi/lo fp16, pre-scaled) ----
    #pragma unroll
    for (int u = 0; u < 4; u++) {
        int row = lrow + u*32;
        uint4 vh = *(const uint4*)&qh_base[(size_t)(q0 + row)*DH_ + lcu*8];
        uint4 vl = *(const uint4*)&ql_base[(size_t)(q0 + row)*DH_ + lcu*8];
        *(uint4*)&Qhi[row*TLD + lcu*8] = vh;
        *(uint4*)&Qlo[row*TLD + lcu*8] = vl;
    }

    float O[8][4];
    #pragma unroll
    for (int n = 0; n < 8; n++)
        #pragma unroll
        for (int t = 0; t < 4; t++) O[n][t] = 0.f;
    float mr0 = -INFINITY, mr1 = -INFINITY;
    float lr0 = 0.f, lr1 = 0.f;

    for (int kt = 0; kt < S_/128; kt++) {
        const int k0g = kt * 128;
        // ---- prefetch K,V (fp16) gmem -> regs ----
        uint4 rk[4], rv[4];
        #pragma unroll
        for (int u = 0; u < 4; u++) {
            int row = lrow + u*32;
            rk[u] = *(const uint4*)&k_base[(size_t)(k0g + row)*DH_ + lcu*8];
            rv[u] = *(const uint4*)&v_base[(size_t)(k0g + row)*DH_ + lcu*8];
        }
        __syncthreads();    // (a) all warps done reading prev K/V
        #pragma unroll
        for (int u = 0; u < 4; u++) {
            int row = lrow + u*32;
            *(uint4*)&Ks[row*TLD + lcu*8] = rk[u];
            *(uint4*)&Vs[row*TLD + lcu*8] = rv[u];
        }
        __syncthreads();    // (b) K/V tile ready

        // ---- S = Q K^T (2-pass: Q hi/lo, K single) ----
        float sacc[16][4];
        #pragma unroll
        for (int n = 0; n < 16; n++)
            #pragma unroll
            for (int t = 0; t < 4; t++) sacc[n][t] = 0.f;

        #pragma unroll
        for (int kk = 0; kk < 64; kk += 16) {
            uint32_t qh[4], ql[4];
            ldsm_x4(qh, aQhi + (kk << 1));
            ldsm_x4(ql, aQlo + (kk << 1));
            #pragma unroll
            for (int np = 0; np < 8; np++) {
                uint32_t kf[4];
                ldsm_x4(kf, aK + ((np*16*TLD + kk) << 1));
                mma16816(sacc[2*np],   qh, kf);
                mma16816(sacc[2*np],   ql, kf);
                mma16816(sacc[2*np+1], qh, kf + 2);
                mma16816(sacc[2*np+1], ql, kf + 2);
            }
        }

        // ---- register softmax (scores already scaled; rows g, g+8) ----
        float mx0 = -INFINITY, mx1 = -INFINITY;
        #pragma unroll
        for (int n = 0; n < 16; n++) {
            mx0 = fmaxf(mx0, fmaxf(sacc[n][0], sacc[n][1]));
            mx1 = fmaxf(mx1, fmaxf(sacc[n][2], sacc[n][3]));
        }
        mx0 = fmaxf(mx0, __shfl_xor_sync(0xffffffffu, mx0, 1));
        mx0 = fmaxf(mx0, __shfl_xor_sync(0xffffffffu, mx0, 2));
        mx1 = fmaxf(mx1, __shfl_xor_sync(0xffffffffu, mx1, 1));
        mx1 = fmaxf(mx1, __shfl_xor_sync(0xffffffffu, mx1, 2));
        float m0n = fmaxf(mr0, mx0), m1n = fmaxf(mr1, mx1);
        float al0 = __expf(mr0 - m0n), al1 = __expf(mr1 - m1n);
        mr0 = m0n; mr1 = m1n;

        uint32_t pa[8][4];
        float sum0 = 0.f, sum1 = 0.f;
        #pragma unroll
        for (int j = 0; j < 8; j++) {
            float p00 = __expf(sacc[2*j][0] - m0n);
            float p01 = __expf(sacc[2*j][1] - m0n);
            float p10 = __expf(sacc[2*j][2] - m1n);
            float p11 = __expf(sacc[2*j][3] - m1n);
            float p04 = __expf(sacc[2*j+1][0] - m0n);
            float p05 = __expf(sacc[2*j+1][1] - m0n);
            float p14 = __expf(sacc[2*j+1][2] - m1n);
            float p15 = __expf(sacc[2*j+1][3] - m1n);
            sum0 += p00 + p01 + p04 + p05;
            sum1 += p10 + p11 + p14 + p15;
            pa[j][0] = h2_to_u32(__floats2half2_rn(p00, p01));
            pa[j][1] = h2_to_u32(__floats2half2_rn(p10, p11));
            pa[j][2] = h2_to_u32(__floats2half2_rn(p04, p05));
            pa[j][3] = h2_to_u32(__floats2half2_rn(p14, p15));
        }
        sum0 += __shfl_xor_sync(0xffffffffu, sum0, 1);
        sum0 += __shfl_xor_sync(0xffffffffu, sum0, 2);
        sum1 += __shfl_xor_sync(0xffffffffu, sum1, 1);
        sum1 += __shfl_xor_sync(0xffffffffu, sum1, 2);
        lr0 = lr0*al0 + sum0;
        lr1 = lr1*al1 + sum1;

        // ---- O rescale + PV (single pass; V via ldmatrix.trans) ----
        #pragma unroll
        for (int n = 0; n < 8; n++) {
            O[n][0] *= al0; O[n][1] *= al0;
            O[n][2] *= al1; O[n][3] *= al1;
        }
        #pragma unroll
        for (int j = 0; j < 8; j++) {
            #pragma unroll
            for (int nvp = 0; nvp < 4; nvp++) {
                uint32_t vf[4];
                ldsm_x4_t(vf, aV + ((j*16*TLD + nvp*16) << 1));
                mma16816(O[2*nvp],   pa[j], vf);
                mma16816(O[2*nvp+1], pa[j], vf + 2);
            }
        }
    }

    // ---- normalize + write [B,S,D] ----
    const int g = lane >> 2;
    const int c = lane & 3;
    const int b = bh >> 4, h = bh & 15;
    float il0 = 1.0f / lr0, il1 = 1.0f / lr1;
    const int r0 = q0 + m0 + g, r1 = r0 + 8;
    #pragma unroll
    for (int nv = 0; nv < 8; nv++) {
        int col = h*DH_ + nv*8 + 2*c;
        float2 v0 = make_float2(O[nv][0]*il0, O[nv][1]*il0);
        float2 v1 = make_float2(O[nv][2]*il1, O[nv][3]*il1);
        *(float2*)&g_att[((size_t)(b*S_ + r0))*D_ + col] = v0;
        *(float2*)&g_att[((size_t)(b*S_ + r1))*D_ + col] = v1;
    }
}

// =====================================================================
// Launch
// =====================================================================
extern "C" void kernel_launch(void* const* d_in, const int* in_sizes, int n_in,
                              void* d_out, int out_size)
{
    const float* query  = (const float*)d_in[0];
    const float* keys   = (const float*)d_in[1];
    const float* values = (const float*)d_in[2];
    const float* Wq = (const float*)d_in[3];
    const float* bq = (const float*)d_in[4];
    const float* Wk = (const float*)d_in[5];
    const float* bk = (const float*)d_in[6];
    const float* Wv = (const float*)d_in[7];
    const float* bv = (const float*)d_in[8];
    const float* Wo = (const float*)d_in[9];
    const float* bo = (const float*)d_in[10];
    float* out = (float*)d_out;

    __half *qhp, *qlp, *khp, *vhp;
    float *ap;
    cudaGetSymbolAddress((void**)&qhp, g_qh);
    cudaGetSymbolAddress((void**)&qlp, g_ql);
    cudaGetSymbolAddress((void**)&khp, g_kh);
    cudaGetSymbolAddress((void**)&vhp, g_vh);
    cudaGetSymbolAddress((void**)&ap,  g_att);

    cudaFuncSetAttribute(gemm_wmma<0>,
                         cudaFuncAttributeMaxDynamicSharedMemorySize, GW_SMEM);
    cudaFuncSetAttribute(gemm_wmma<1>,
                         cudaFuncAttributeMaxDynamicSharedMemorySize, GW_SMEM);
    cudaFuncSetAttribute(gemm_wmma<2>,
                         cudaFuncAttributeMaxDynamicSharedMemorySize, GW_SMEM);
    cudaFuncSetAttribute(attn_mma,
                         cudaFuncAttributeMaxDynamicSharedMemorySize, ATT_SMEM);

    dim3 gemm_grid(D_/128, M_/128);   // (8, 32)
    gemm_wmma<1><<<gemm_grid, 256, GW_SMEM>>>(query,  Wq, bq, nullptr, qhp, qlp);
    gemm_wmma<2><<<gemm_grid, 256, GW_SMEM>>>(keys,   Wk, bk, nullptr, khp, nullptr);
    gemm_wmma<2><<<gemm_grid, 256, GW_SMEM>>>(values, Wv, bv, nullptr, vhp, nullptr);

    attn_mma<<<dim3(S_/128, B_*H_), 256, ATT_SMEM>>>();

    gemm_wmma<0><<<gemm_grid, 256, GW_SMEM>>>(ap, Wo, bo, out, nullptr, nullptr);
}